// round 13
// baseline (speedup 1.0000x reference)
#include <cuda_runtime.h>
#include <cuda_bf16.h>
#include <math.h>
#include <stdint.h>

#define Bc 2048
#define Dc 24
#define Hc 256
#define Lc 64
#define Vc 780
#define Tc 23
#define Sc 47
#define DB (Dc*Bc)
#define TB (Tc*Bc)
#define SB (Sc*Bc)
#define QP (DB/128)
#define PBLOCKS (SB/8)
#define WROWS 3200

// ---------------- fp32 scratch ---------------------------------------------
__device__ float g_Az[DB*Hc];
__device__ float g_Ah[DB*Hc];
__device__ float g_Ar[DB*Hc];
__device__ float g_Px[DB*Hc];
__device__ float g_Pq [TB*Hc];
__device__ float g_Pmf[TB*Hc];
__device__ float g_Pmr[TB*Hc];
__device__ float g_Tq[Bc*Hc];
__device__ float g_Tp[Bc*Hc];
__device__ float g_qpart_loss[QP];
__device__ float g_qpart_corr[QP];
__device__ float g_ppart_loss[PBLOCKS];
__device__ float g_ppart_corr[PBLOCKS];
// bf16 split planes
__device__ __nv_bfloat16 g_wH[(size_t)WROWS*Hc];
__device__ __nv_bfloat16 g_wL[(size_t)WROWS*Hc];
__device__ __nv_bfloat16 g_eH[(size_t)Vc*Hc];
__device__ __nv_bfloat16 g_eL[(size_t)Vc*Hc];
__device__ __nv_bfloat16 g_mH[(size_t)2*TB*Hc];   // [dir][t*Bc+b][Hc]
__device__ __nv_bfloat16 g_mL[(size_t)2*TB*Hc];
__device__ __nv_bfloat16 g_rmH[(size_t)2*Bc*Hc];  // [dir][b][Hc]
__device__ __nv_bfloat16 g_rmL[(size_t)2*Bc*Hc];

__device__ __forceinline__ float sigf(float x) { return 1.f / (1.f + expf(-x)); }

// =================== mma.sync core =========================================
__device__ __forceinline__ uint32_t s2u(const void* p) {
    uint32_t a;
    asm("{ .reg .u64 t; cvta.to.shared.u64 t, %1; cvt.u32.u64 %0, t; }" : "=r"(a) : "l"(p));
    return a;
}
__device__ __forceinline__ void ldsm4(uint32_t& r0, uint32_t& r1, uint32_t& r2, uint32_t& r3, uint32_t a) {
    asm volatile("ldmatrix.sync.aligned.m8n8.x4.shared.b16 {%0,%1,%2,%3}, [%4];"
        : "=r"(r0), "=r"(r1), "=r"(r2), "=r"(r3) : "r"(a));
}
__device__ __forceinline__ void mma16816(float* d,
    uint32_t a0, uint32_t a1, uint32_t a2, uint32_t a3, uint32_t b0, uint32_t b1) {
    asm volatile("mma.sync.aligned.m16n8k16.row.col.f32.bf16.bf16.f32 "
        "{%0,%1,%2,%3}, {%4,%5,%6,%7}, {%8,%9}, {%0,%1,%2,%3};"
        : "+f"(d[0]), "+f"(d[1]), "+f"(d[2]), "+f"(d[3])
        : "r"(a0), "r"(a1), "r"(a2), "r"(a3), "r"(b0), "r"(b1));
}
__device__ __forceinline__ void pass_mma(uint32_t aAddr, uint32_t bAddr, float acc[2][4][4]) {
    uint32_t b0, b1, b2, b3, b4, b5, b6, b7;
    ldsm4(b0, b1, b2, b3, bAddr);
    ldsm4(b4, b5, b6, b7, bAddr + 1280);
#pragma unroll
    for (int mf = 0; mf < 2; mf++) {
        uint32_t a0, a1, a2, a3;
        ldsm4(a0, a1, a2, a3, aAddr + mf * 1280);
        mma16816(acc[mf][0], a0, a1, a2, a3, b0, b1);
        mma16816(acc[mf][1], a0, a1, a2, a3, b2, b3);
        mma16816(acc[mf][2], a0, a1, a2, a3, b4, b5);
        mma16816(acc[mf][3], a0, a1, a2, a3, b6, b7);
    }
}
// 16-col-strip, M=64 fused 3-product pass (10 ldsm, 24 mma)
__device__ __forceinline__ void pass3_16x4(uint32_t ah, uint32_t al, uint32_t bh, uint32_t bl,
                                           float acc[4][2][4]) {
    uint32_t h0,h1,h2,h3, l0,l1,l2,l3;
    ldsm4(h0,h1,h2,h3, bh);
    ldsm4(l0,l1,l2,l3, bl);
#pragma unroll
    for (int mf = 0; mf < 4; mf++) {
        uint32_t a0,a1,a2,a3, c0,c1,c2,c3;
        ldsm4(a0,a1,a2,a3, ah + mf * 1280);
        ldsm4(c0,c1,c2,c3, al + mf * 1280);
        mma16816(acc[mf][0], a0,a1,a2,a3, h0,h1);
        mma16816(acc[mf][1], a0,a1,a2,a3, h2,h3);
        mma16816(acc[mf][0], a0,a1,a2,a3, l0,l1);
        mma16816(acc[mf][1], a0,a1,a2,a3, l2,l3);
        mma16816(acc[mf][0], c0,c1,c2,c3, h0,h1);
        mma16816(acc[mf][1], c0,c1,c2,c3, h2,h3);
    }
}
__device__ __forceinline__ uint32_t aLaneOff(int lane, int wm) {
    return (uint32_t)((lane & 15) * 80 + (lane >> 4) * 16 + wm * 2560);
}
__device__ __forceinline__ uint32_t bLaneOff(int lane, int wn) {
    return (uint32_t)((((lane & 7) + ((lane >> 4) & 1) * 8)) * 80 + ((lane >> 3) & 1) * 16 + wn * 2560);
}
__device__ __forceinline__ uint32_t packbf2(float a, float b) {
    __nv_bfloat162 v = __floats2bfloat162_rn(a, b);
    return *(uint32_t*)&v;
}
__device__ __forceinline__ float2 unpack2(uint32_t h, uint32_t l) {
    __nv_bfloat162 H = *(__nv_bfloat162*)&h, L = *(__nv_bfloat162*)&l;
    return make_float2(__bfloat162float(H.x) + __bfloat162float(L.x),
                       __bfloat162float(H.y) + __bfloat162float(L.y));
}
// ---- cp.async helpers ----
__device__ __forceinline__ void cpa16(uint32_t dst, const void* src) {
    asm volatile("cp.async.cg.shared.global [%0], [%1], 16;" :: "r"(dst), "l"(src));
}
#define CPC()  asm volatile("cp.async.commit_group;" ::: "memory")
#define CPW(n) asm volatile("cp.async.wait_group %0;" :: "n"(n) : "memory")

// ------------- split/convert kernels ---------------------------------------
__global__ void k_split_w(const float* __restrict__ Wz, const float* __restrict__ Wh,
                          const float* __restrict__ Wr, const float* __restrict__ Ur,
                          const float* __restrict__ U_w, const float* __restrict__ W_w,
                          const float* __restrict__ Wo_w)
{
    int r = blockIdx.x, c = threadIdx.x;
    float v;
    if      (r < 256)  v = Wz[r * 512 + c];
    else if (r < 512)  v = Wh[(r - 256) * 512 + c];
    else if (r < 768)  v = Wr[(r - 512) * 256 + c];
    else if (r < 1024) v = U_w[(r - 768) * 576 + c];
    else if (r < 1280) v = W_w[(r - 1024) * 320 + c];
    else if (r < 1536) v = U_w[(r - 1280) * 576 + 256 + c];
    else if (r < 2432) { int w = r - 1536; v = (w < Vc) ? Wo_w[(size_t)w * 256 + c] : 0.f; }
    else if (r < 2688) v = Wz[(r - 2432) * 512 + 256 + c];
    else if (r < 2944) v = Wh[(r - 2688) * 512 + 256 + c];
    else               v = Ur[(r - 2944) * 256 + c];
    __nv_bfloat16 h = __float2bfloat16(v);
    g_wH[(size_t)r * 256 + c] = h;
    g_wL[(size_t)r * 256 + c] = __float2bfloat16(v - __bfloat162float(h));
}

__global__ void k_split_emb(const float* __restrict__ emb)
{
    int r = blockIdx.x, c = threadIdx.x;
    float v = emb[(size_t)r * 256 + c];
    __nv_bfloat16 h = __float2bfloat16(v);
    g_eH[(size_t)r * 256 + c] = h;
    g_eL[(size_t)r * 256 + c] = __float2bfloat16(v - __bfloat162float(h));
}

// ------------- generic big GEMM (HMMA, CTA 128x64, double-buffered) --------
#define TCG_BUF 30720
#define TCG_DSM 61440
__global__ void __launch_bounds__(256, 3) k_tcg(int modeBase, const int* __restrict__ wid,
                      const float* __restrict__ bz, const float* __restrict__ bh,
                      const float* __restrict__ br)
{
    extern __shared__ char smc[];
    uint32_t smb = s2u(smc);
    int tid = threadIdx.x, lane = tid & 31, warp = tid >> 5;
    int wm = warp >> 1, wn = warp & 1;
    int mode = modeBase + blockIdx.z;
    int rowBase = blockIdx.x * 128, colBase = blockIdx.y * 64;

    int wbase; float* outp; const float* bias;
    switch (mode) {
        case 0: wbase = 0;    outp = g_Az;  bias = bz; break;
        case 1: wbase = 256;  outp = g_Ah;  bias = bh; break;
        case 2: wbase = 512;  outp = g_Ar;  bias = br; break;
        case 3: wbase = 768;  outp = g_Px;  bias = 0;  break;
        case 4: wbase = 1024; outp = g_Pq;  bias = 0;  break;
        case 5: wbase = 1280; outp = g_Pmf; bias = 0;  break;
        default: wbase = 1280; outp = g_Pmr; bias = 0; break;
    }

    const uint4 *aHp[2], *aLp[2];
    uint32_t aStore[2];
#pragma unroll
    for (int j = 0; j < 2; j++) {
        int idx = tid + j * 256;
        int row = idx >> 2, q = idx & 3;
        aStore[j] = (uint32_t)(row * 80 + q * 16);
        int rA = rowBase + row;
        if (mode < 4) {
            int d = rA >> 11, b = rA & 2047;
            int sr = wid[b * Dc + d];
            aHp[j] = (const uint4*)(g_eH + (size_t)sr * 256 + q * 8);
            aLp[j] = (const uint4*)(g_eL + (size_t)sr * 256 + q * 8);
        } else {
            size_t rs = (size_t)((mode == 6) ? TB : 0) + rA;
            aHp[j] = (const uint4*)(g_mH + rs * 256 + q * 8);
            aLp[j] = (const uint4*)(g_mL + rs * 256 + q * 8);
        }
    }
    int bRow = tid >> 2, bQ = tid & 3;
    uint32_t bStore = (uint32_t)(bRow * 80 + bQ * 16);
    const uint4* bHp = (const uint4*)(g_wH + (size_t)(wbase + colBase + bRow) * 256 + bQ * 8);
    const uint4* bLp = (const uint4*)(g_wL + (size_t)(wbase + colBase + bRow) * 256 + bQ * 8);

    uint32_t aOff = aLaneOff(lane, wm), bOff = bLaneOff(lane, wn);
    float acc[2][4][4] = {};

    auto stage = [&](int kc) {
        uint32_t bo = smb + (uint32_t)((kc & 1) * TCG_BUF);
#pragma unroll
        for (int j = 0; j < 2; j++) {
            cpa16(bo + aStore[j],         aHp[j] + kc * 4);
            cpa16(bo + 10240 + aStore[j], aLp[j] + kc * 4);
        }
        cpa16(bo + 20480 + bStore, bHp + kc * 4);
        cpa16(bo + 25600 + bStore, bLp + kc * 4);
        CPC();
    };

    stage(0);
    for (int kc = 0; kc < 8; kc++) {
        if (kc < 7) { stage(kc + 1); CPW(1); }
        else        { CPW(0); }
        __syncthreads();
        uint32_t bo = smb + (uint32_t)((kc & 1) * TCG_BUF);
#pragma unroll
        for (int kk = 0; kk < 2; kk++) {
            uint32_t kb = kk * 32;
            pass_mma(bo + aOff + kb,         bo + 20480 + bOff + kb, acc);
            pass_mma(bo + aOff + kb,         bo + 25600 + bOff + kb, acc);
            pass_mma(bo + 10240 + aOff + kb, bo + 20480 + bOff + kb, acc);
        }
        __syncthreads();
    }

    float* stg = (float*)smc + warp * (32 * 33);
#pragma unroll
    for (int mf = 0; mf < 2; mf++)
#pragma unroll
        for (int nf = 0; nf < 4; nf++) {
            int r = mf * 16 + (lane >> 2);
            int c = nf * 8 + ((lane & 3) << 1);
            stg[r * 33 + c]           = acc[mf][nf][0];
            stg[r * 33 + c + 1]       = acc[mf][nf][1];
            stg[(r + 8) * 33 + c]     = acc[mf][nf][2];
            stg[(r + 8) * 33 + c + 1] = acc[mf][nf][3];
        }
    __syncwarp();
    int colg = colBase + wn * 32 + lane;
    float bval = bias ? bias[colg] : 0.f;
#pragma unroll 8
    for (int r = 0; r < 32; r++) {
        int rowg = rowBase + wm * 32 + r;
        outp[(size_t)rowg * 256 + colg] = stg[r * 33 + lane] + bval;
    }
}

// ------------- tree_vec small GEMMs ----------------------------------------
__global__ void k_tree(const float* __restrict__ tv,
                       const float* __restrict__ W_w, const float* __restrict__ W_b,
                       const float* __restrict__ U_w, const float* __restrict__ U_b)
{
    int b = blockIdx.x, z = blockIdx.y, n = threadIdx.x;
    __shared__ float s_tv[Lc];
    if (n < Lc) s_tv[n] = tv[(size_t)b * Lc + n];
    __syncthreads();
    const float* W; int ld, koff; const float* bias; float* out;
    if (z == 0) { W = W_w; ld = Hc + Lc;   koff = Hc;   bias = W_b; out = g_Tq; }
    else        { W = U_w; ld = 2*Hc + Lc; koff = 2*Hc; bias = U_b; out = g_Tp; }
    const float* wr = W + (size_t)n * ld + koff;
    float s = bias[n];
#pragma unroll
    for (int k = 0; k < Lc; k += 4) {
        float4 w4 = *(const float4*)(wr + k);
        s += s_tv[k]*w4.x + s_tv[k+1]*w4.y + s_tv[k+2]*w4.z + s_tv[k+3]*w4.w;
    }
    out[(size_t)b * Hc + n] = s;
}

// ------------- fused row-local scan: 64 CTAs x 64 rows, 512 threads --------
// dir = bid>>5, rows rb..rb+63 (rb = (bid&31)*64), all 256 cols.
// 16 warps: warp wn covers cols wn*16..+15, M=64 (4 fragments/warp).
// m resident in smem (80KB); weights double-buffered (80KB); r*m round-trips
// through global with per-chunk cp.async staging (16KB) in segment G2.
#define SC_MRES  0          /* 8 chunks x [H 5120 | L 5120] = 81920 */
#define SC_WBUF  81920      /* 2 x 40960 */
#define SC_RMBUF 163840     /* 2 x 10240: per slot [H 5120 | L 5120] */
#define SC_DSM   184320
__global__ void __launch_bounds__(512, 1) k_scan()
{
    extern __shared__ char smc[];
    uint32_t smb = s2u(smc);
    int tid = threadIdx.x, lane = tid & 31, warp = tid >> 5;  // warp 0..15
    int wn = warp;
    int dir = blockIdx.x >> 5;
    int rb = (blockIdx.x & 31) * 64;

    uint32_t aOff = aLaneOff(lane, 0);
    uint32_t bOff = (uint32_t)((((lane & 7) + ((lane >> 4) & 1) * 8)) * 80
                  + ((lane >> 3) & 1) * 16 + wn * 1280);

    // stage weight chunk kc (rows wb..wb+255) into weight buffer slot kc&1;
    // optionally stage rm chunk into rm buffer slot kc&1. One commit group.
    auto stage = [&](int wb, int kc, bool withRM) {
        uint32_t bo = smb + SC_WBUF + (uint32_t)((kc & 1) * 40960);
#pragma unroll
        for (int i = 0; i < 4; i++) {
            int u = tid + i * 512;          // 0..2047
            int pl = u >= 1024;
            int uu = u - pl * 1024;
            int col = uu >> 2, q = uu & 3;
            const __nv_bfloat16* src = (pl ? g_wL : g_wH)
                + (size_t)(wb + col) * 256 + kc * 32 + q * 8;
            cpa16(bo + pl * 20480 + col * 80 + q * 16, src);
        }
        if (withRM) {
            uint32_t ro = smb + SC_RMBUF + (uint32_t)((kc & 1) * 10240);
            int pl = tid >= 256;
            int uu = tid - pl * 256;        // 0..255
            int row = uu >> 2, q = uu & 3;  // row 0..63
            const __nv_bfloat16* src = (pl ? g_rmL : g_rmH)
                + ((size_t)dir * Bc + rb + row) * 256 + kc * 32 + q * 8;
            cpa16(ro + pl * 5120 + row * 80 + q * 16, src);
        }
        CPC();
    };

    // one 8-chunk segment (double-buffered, R11-proven pattern)
    auto segment = [&](int wb, bool useRM, float acc[4][2][4]) {
        stage(wb, 0, useRM);
        for (int kc = 0; kc < 8; kc++) {
            if (kc < 7) { stage(wb, kc + 1, useRM); CPW(1); }
            else        { CPW(0); }
            __syncthreads();
            uint32_t bo = smb + SC_WBUF + (uint32_t)((kc & 1) * 40960);
            uint32_t aH = useRM
                ? smb + SC_RMBUF + (uint32_t)((kc & 1) * 10240) + aOff
                : smb + SC_MRES + (uint32_t)(kc * 10240) + aOff;
            uint32_t aL = aH + 5120;
#pragma unroll
            for (int kk = 0; kk < 2; kk++) {
                uint32_t kb = kk * 32;
                pass3_16x4(aH + kb, aL + kb,
                           bo + bOff + kb, bo + 20480 + bOff + kb, acc);
            }
            __syncthreads();
        }
    };

    for (int t = 0; t < Tc; t++) {
        int srcd = dir ? (Tc - t) : t;
        float accz[4][2][4] = {}, acch[4][2][4] = {};

        if (t > 0) {
            segment(2432, false, accz);   // accz = m(t-1) @ Uz^T   (A: resident m)
            segment(2688, true,  acch);   // acch = rm     @ Uh^T   (A: staged rm)
        }

        // -------- phase A epilogue: GRU update; Az/Ah via __ldg ------------
        size_t gRowBase = (size_t)dir * TB + (size_t)t * Bc + rb;
#pragma unroll
        for (int mf = 0; mf < 4; mf++)
#pragma unroll
            for (int nf = 0; nf < 2; nf++) {
#pragma unroll
                for (int h = 0; h < 2; h++) {
                    int row = mf * 16 + (lane >> 2) + h * 8;   // 0..63
                    int col = wn * 16 + nf * 8 + ((lane & 3) << 1);
                    size_t ro = ((size_t)srcd * Bc + rb + row) * 256 + col;
                    float2 az = __ldg((const float2*)(g_Az + ro));
                    float2 ah = __ldg((const float2*)(g_Ah + ro));
                    int chunk = col >> 5, k = col & 31, q = k >> 3, byo = (k & 7) * 2;
                    uint32_t mo = SC_MRES + chunk * 10240 + row * 80 + q * 16 + byo;
                    float2 mp = make_float2(0.f, 0.f);
                    if (t > 0)
                        mp = unpack2(*(uint32_t*)(smc + mo), *(uint32_t*)(smc + mo + 5120));
                    float z0 = sigf(accz[mf][nf][h*2+0] + az.x);
                    float z1 = sigf(accz[mf][nf][h*2+1] + az.y);
                    float q0 = tanhf(acch[mf][nf][h*2+0] + ah.x);
                    float q1 = tanhf(acch[mf][nf][h*2+1] + ah.y);
                    float m0 = (1.f - z0) * mp.x + z0 * q0;
                    float m1 = (1.f - z1) * mp.y + z1 * q1;
                    __nv_bfloat16 h0 = __float2bfloat16(m0), h1 = __float2bfloat16(m1);
                    uint32_t hv = packbf2(__bfloat162float(h0), __bfloat162float(h1));
                    uint32_t lv = packbf2(m0 - __bfloat162float(h0), m1 - __bfloat162float(h1));
                    *(uint32_t*)(smc + mo) = hv;
                    *(uint32_t*)(smc + mo + 5120) = lv;
                    size_t po = (gRowBase + row) * 256 + col;
                    *(uint32_t*)(g_mH + po) = hv;
                    *(uint32_t*)(g_mL + po) = lv;
                }
            }
        __syncthreads();

        if (t == Tc - 1) break;

        // -------- phase B: acc = m(t) @ Ur^T; rm = sigmoid(acc+Ar)*m -------
        {
            int dstd = dir ? (Tc - 1 - t) : (t + 1);
            float acc[4][2][4] = {};
            segment(2944, false, acc);
#pragma unroll
            for (int mf = 0; mf < 4; mf++)
#pragma unroll
                for (int nf = 0; nf < 2; nf++) {
#pragma unroll
                    for (int h = 0; h < 2; h++) {
                        int row = mf * 16 + (lane >> 2) + h * 8;
                        int col = wn * 16 + nf * 8 + ((lane & 3) << 1);
                        float2 ar = __ldg((const float2*)(
                            g_Ar + ((size_t)dstd * Bc + rb + row) * 256 + col));
                        int chunk = col >> 5, k = col & 31, q = k >> 3, byo = (k & 7) * 2;
                        uint32_t mo = SC_MRES + chunk * 10240 + row * 80 + q * 16 + byo;
                        float2 mc = unpack2(*(uint32_t*)(smc + mo), *(uint32_t*)(smc + mo + 5120));
                        float r0 = sigf(acc[mf][nf][h*2+0] + ar.x);
                        float r1 = sigf(acc[mf][nf][h*2+1] + ar.y);
                        float rm0 = r0 * mc.x, rm1 = r1 * mc.y;
                        __nv_bfloat16 h0 = __float2bfloat16(rm0), h1 = __float2bfloat16(rm1);
                        size_t po = ((size_t)dir * Bc + rb + row) * 256 + col;
                        *(uint32_t*)(g_rmH + po) = packbf2(__bfloat162float(h0), __bfloat162float(h1));
                        *(uint32_t*)(g_rmL + po) = packbf2(rm0 - __bfloat162float(h0), rm1 - __bfloat162float(h1));
                    }
                }
            __syncthreads();
        }
    }
}

// ------------- fused q-head ------------------------------------------------
#define QH_B0   163840
#define QH_STG  184320
#define QH_BIAS 217600
#define QH_RED  217856
#define QH_DSM  218880
__global__ void k_qhead(const int* __restrict__ wid, const float* __restrict__ Wob)
{
    extern __shared__ char smc[];
    uint32_t smb = s2u(smc);
    int tid = threadIdx.x, lane = tid & 31, warp = tid >> 5;
    int wm = warp >> 1, wn = warp & 1;
    int rowBase = blockIdx.x * 128;

    for (int it = 0; it < 16; it++) {
        int idx = tid + it * 256;
        int row = idx >> 5, rem = idx & 31, kc = rem >> 2, q = rem & 3;
        int rA = rowBase + row, d = rA >> 11, b = rA & 2047;
        int k0 = kc * 32 + q * 8;
        const float4* tq = (const float4*)(g_Tq + (size_t)b * 256 + k0);
        float4 v0 = tq[0], v1 = tq[1];
        if (d) {
            const float4* pq = (const float4*)(g_Pq + ((size_t)(d - 1) * Bc + b) * 256 + k0);
            float4 p0 = pq[0], p1 = pq[1];
            v0.x += p0.x; v0.y += p0.y; v0.z += p0.z; v0.w += p0.w;
            v1.x += p1.x; v1.y += p1.y; v1.z += p1.z; v1.w += p1.w;
        }
        float vv[8] = { fmaxf(v0.x,0.f), fmaxf(v0.y,0.f), fmaxf(v0.z,0.f), fmaxf(v0.w,0.f),
                        fmaxf(v1.x,0.f), fmaxf(v1.y,0.f), fmaxf(v1.z,0.f), fmaxf(v1.w,0.f) };
        union { uint4 u; __nv_bfloat16 b8[8]; } Hx, Lx;
#pragma unroll
        for (int e = 0; e < 8; e++) {
            Hx.b8[e] = __float2bfloat16(vv[e]);
            Lx.b8[e] = __float2bfloat16(vv[e] - __bfloat162float(Hx.b8[e]));
        }
        uint32_t off = (uint32_t)(kc * 10240 + row * 80 + q * 16);
        *(uint4*)(smc + off) = Hx.u;
        *(uint4*)(smc + 81920 + off) = Lx.u;
    }
    __syncthreads();

    int myrow = tid >> 1, half = tid & 1;
    int rA0 = rowBase + myrow;
    int tgt = wid[(rA0 & 2047) * Dc + (rA0 >> 11)];
    float runMax = -3.4e38f, runSum = 0.f, sel = 0.f;
    int runIdx = Vc;

    uint32_t aOff = aLaneOff(lane, wm), bOff = bLaneOff(lane, wn);
    int bRow = tid >> 2, bQ = tid & 3;
    uint32_t bStore = (uint32_t)(bRow * 80 + bQ * 16);
    float* stg = (float*)(smc + QH_STG);
    float* s_bias = (float*)(smc + QH_BIAS);

    for (int cb = 0; cb < 13; cb++) {
        if (tid < 64) {
            int colg = cb * 64 + tid;
            s_bias[tid] = (colg < Vc) ? Wob[colg] : 0.f;
        }
        float acc[2][4][4] = {};
        const uint4* bh = (const uint4*)(g_wH + (size_t)(1536 + cb * 64 + bRow) * 256 + bQ * 8);
        const uint4* bl = (const uint4*)(g_wL + (size_t)(1536 + cb * 64 + bRow) * 256 + bQ * 8);
        auto stageB = [&](int kc) {
            uint32_t bo = smb + QH_B0 + (uint32_t)((kc & 1) * 10240);
            cpa16(bo + bStore, bh + kc * 4);
            cpa16(bo + 5120 + bStore, bl + kc * 4);
            CPC();
        };
        stageB(0);
        for (int kc = 0; kc < 8; kc++) {
            if (kc < 7) { stageB(kc + 1); CPW(1); }
            else        { CPW(0); }
            __syncthreads();
            uint32_t bo = smb + QH_B0 + (uint32_t)((kc & 1) * 10240);
#pragma unroll
            for (int kk = 0; kk < 2; kk++) {
                uint32_t kb = kk * 32;
                pass_mma(smb + kc * 10240 + aOff + kb,         bo + bOff + kb, acc);
                pass_mma(smb + kc * 10240 + aOff + kb,         bo + 5120 + bOff + kb, acc);
                pass_mma(smb + 81920 + kc * 10240 + aOff + kb, bo + bOff + kb, acc);
            }
            __syncthreads();
        }
#pragma unroll
        for (int mf = 0; mf < 2; mf++)
#pragma unroll
            for (int nf = 0; nf < 4; nf++) {
                int r = wm * 32 + mf * 16 + (lane >> 2);
                int c = wn * 32 + nf * 8 + ((lane & 3) << 1);
                stg[r * 65 + c]           = acc[mf][nf][0];
                stg[r * 65 + c + 1]       = acc[mf][nf][1];
                stg[(r + 8) * 65 + c]     = acc[mf][nf][2];
                stg[(r + 8) * 65 + c + 1] = acc[mf][nf][3];
            }
        __syncthreads();
        int colBaseT = cb * 64 + half * 32;
#pragma unroll 8
        for (int j = 0; j < 32; j++) {
            int col = colBaseT + j;
            if (col < Vc) {
                float v = stg[myrow * 65 + half * 32 + j] + s_bias[half * 32 + j];
                if (v > runMax) {
                    runSum = runSum * expf(runMax - v) + 1.f;
                    runMax = v; runIdx = col;
                } else {
                    runSum += expf(v - runMax);
                }
                if (col == tgt) sel = v;
            }
        }
        __syncthreads();
    }

    float oMax = __shfl_xor_sync(0xffffffffu, runMax, 1);
    float oSum = __shfl_xor_sync(0xffffffffu, runSum, 1);
    float oSel = __shfl_xor_sync(0xffffffffu, sel, 1);
    int   oIdx = __shfl_xor_sync(0xffffffffu, runIdx, 1);
    float M = fmaxf(runMax, oMax);
    float S = runSum * expf(runMax - M) + oSum * expf(oMax - M);
    int I = (oMax > runMax || (oMax == runMax && oIdx < runIdx)) ? oIdx : runIdx;
    float SEL = sel + oSel;

    float* lred = (float*)(smc + QH_RED);
    float* cred = lred + 128;
    if (half == 0) {
        lred[myrow] = (M + logf(S)) - SEL;
        cred[myrow] = (I == tgt) ? 1.f : 0.f;
    }
    __syncthreads();
    for (int o = 64; o; o >>= 1) {
        if (tid < o) { lred[tid] += lred[tid + o]; cred[tid] += cred[tid + o]; }
        __syncthreads();
    }
    if (tid == 0) {
        g_qpart_loss[blockIdx.x] = lred[0];
        g_qpart_corr[blockIdx.x] = cred[0];
    }
}

// ------------- p-head ------------------------------------------------------
__global__ void k_p(const float* __restrict__ usw, const float* __restrict__ usb)
{
    int warp = threadIdx.x >> 5, lane = threadIdx.x & 31;
    int row = blockIdx.x * 8 + warp;
    int s = row >> 11, b = row & (Bc - 1);

    int xd, c1, c2;
    if (s == 0)       { xd = 0; c1 = -1; c2 = -1; }
    else if (s <= Tc) { xd = s; c1 = s - 1; c2 = -1; }
    else { int j = s - (Tc + 1); xd = Tc - 1 - j; c1 = (j <= Tc - 2) ? (Tc - 2 - j) : -1; c2 = j; }

    const float* px = g_Px + ((size_t)xd * Bc + b) * Hc;
    const float* tp = g_Tp + (size_t)b * Hc;
    const float* f1 = (c1 >= 0) ? (g_Pmf + ((size_t)c1 * Bc + b) * Hc) : (const float*)0;
    const float* f2 = (c2 >= 0) ? (g_Pmr + ((size_t)c2 * Bc + b) * Hc) : (const float*)0;

    float acc = 0.f;
#pragma unroll
    for (int i = 0; i < 2; i++) {
        int n = (lane + 32 * i) * 4;
        float4 v = *(const float4*)(px + n);
        float4 t4 = *(const float4*)(tp + n);
        v.x += t4.x; v.y += t4.y; v.z += t4.z; v.w += t4.w;
        if (f1) { float4 a4 = *(const float4*)(f1 + n); v.x+=a4.x; v.y+=a4.y; v.z+=a4.z; v.w+=a4.w; }
        if (f2) { float4 a4 = *(const float4*)(f2 + n); v.x+=a4.x; v.y+=a4.y; v.z+=a4.z; v.w+=a4.w; }
        v.x = fmaxf(v.x,0.f); v.y = fmaxf(v.y,0.f); v.z = fmaxf(v.z,0.f); v.w = fmaxf(v.w,0.f);
        float4 u = *(const float4*)(usw + n);
        acc += v.x*u.x + v.y*u.y + v.z*u.z + v.w*u.w;
    }
#pragma unroll
    for (int o = 16; o; o >>= 1) acc += __shfl_xor_sync(0xffffffffu, acc, o);

    __shared__ float sl[8], sc[8];
    if (lane == 0) {
        float p = acc + usb[0];
        int tchk = (s < Tc) ? 1 : 0;
        float loss = fmaxf(p, 0.f) - (tchk ? p : 0.f) + log1pf(expf(-fabsf(p)));
        float corr = (((p > 0.f) ? 1 : 0) == tchk) ? 1.f : 0.f;
        sl[warp] = loss; sc[warp] = corr;
    }
    __syncthreads();
    if (threadIdx.x == 0) {
        float a = 0.f, c = 0.f;
        for (int w = 0; w < 8; w++) { a += sl[w]; c += sc[w]; }
        g_ppart_loss[blockIdx.x] = a;
        g_ppart_corr[blockIdx.x] = c;
    }
}

__global__ void k_finalize(float* __restrict__ out)
{
    __shared__ float sq[256], sqc[256], sp[256], spc[256];
    int t = threadIdx.x;
    float a = 0.f, b = 0.f, c = 0.f, d = 0.f;
    for (int i = t; i < QP; i += 256) { a += g_qpart_loss[i]; b += g_qpart_corr[i]; }
    for (int i = t; i < PBLOCKS; i += 256) { c += g_ppart_loss[i]; d += g_ppart_corr[i]; }
    sq[t] = a; sqc[t] = b; sp[t] = c; spc[t] = d;
    __syncthreads();
    for (int o = 128; o; o >>= 1) {
        if (t < o) { sq[t]+=sq[t+o]; sqc[t]+=sqc[t+o]; sp[t]+=sp[t+o]; spc[t]+=spc[t+o]; }
        __syncthreads();
    }
    if (t == 0) {
        out[0] = sq[0]  / (float)Bc;
        out[1] = sp[0]  / (float)Bc;
        out[2] = sqc[0] / (float)DB;
        out[3] = spc[0] / (float)SB;
    }
}

// ---------------------------------------------------------------------------
extern "C" void kernel_launch(void* const* d_in, const int* in_sizes, int n_in,
                              void* d_out, int out_size)
{
    const int*   wid      = (const int*)  d_in[0];
    const float* tree_vec = (const float*)d_in[1];
    const float* emb      = (const float*)d_in[2];
    const float* Wz       = (const float*)d_in[3];
    const float* bz       = (const float*)d_in[4];
    const float* Wr       = (const float*)d_in[5];
    const float* Ur       = (const float*)d_in[6];
    const float* br       = (const float*)d_in[7];
    const float* Wh       = (const float*)d_in[8];
    const float* bh       = (const float*)d_in[9];
    const float* W_w      = (const float*)d_in[10];
    const float* W_b      = (const float*)d_in[11];
    const float* U_w      = (const float*)d_in[12];
    const float* U_b      = (const float*)d_in[13];
    const float* Wo_w     = (const float*)d_in[14];
    const float* Wo_b     = (const float*)d_in[15];
    const float* Us_w     = (const float*)d_in[16];
    const float* Us_b     = (const float*)d_in[17];
    float* out = (float*)d_out;

    cudaFuncSetAttribute(k_tcg,   cudaFuncAttributeMaxDynamicSharedMemorySize, TCG_DSM);
    cudaFuncSetAttribute(k_scan,  cudaFuncAttributeMaxDynamicSharedMemorySize, SC_DSM);
    cudaFuncSetAttribute(k_qhead, cudaFuncAttributeMaxDynamicSharedMemorySize, QH_DSM);

    k_split_w<<<WROWS, 256>>>(Wz, Wh, Wr, Ur, U_w, W_w, Wo_w);
    k_split_emb<<<Vc, 256>>>(emb);
    k_tree<<<dim3(Bc, 2), 256>>>(tree_vec, W_w, W_b, U_w, U_b);

    k_tcg<<<dim3(DB/128, 4, 4), 256, TCG_DSM>>>(0, wid, bz, bh, br);

    k_scan<<<64, 512, SC_DSM>>>();

    k_tcg<<<dim3(TB/128, 4, 3), 256, TCG_DSM>>>(4, wid, bz, bh, br);
    k_qhead<<<DB/128, 256, QH_DSM>>>(wid, Wo_b);

    k_p<<<PBLOCKS, 256>>>(Us_w, Us_b);
    k_finalize<<<1, 256>>>(out);
}

// round 14
// speedup vs baseline: 1.3558x; 1.3558x over previous
#include <cuda_runtime.h>
#include <cuda_bf16.h>
#include <math.h>
#include <stdint.h>

#define Bc 2048
#define Dc 24
#define Hc 256
#define Lc 64
#define Vc 780
#define Tc 23
#define Sc 47
#define DB (Dc*Bc)
#define TB (Tc*Bc)
#define SB (Sc*Bc)
#define QP (DB/128)
#define PBLOCKS (SB/8)
#define WROWS 3200

// ---------------- fp32 scratch ---------------------------------------------
__device__ float g_Az[DB*Hc];
__device__ float g_Ah[DB*Hc];
__device__ float g_Ar[DB*Hc];
__device__ float g_Px[DB*Hc];
__device__ float g_Pq [TB*Hc];
__device__ float g_Pmf[TB*Hc];
__device__ float g_Pmr[TB*Hc];
__device__ float g_Tq[Bc*Hc];
__device__ float g_Tp[Bc*Hc];
__device__ float g_qpart_loss[QP];
__device__ float g_qpart_corr[QP];
__device__ float g_ppart_loss[PBLOCKS];
__device__ float g_ppart_corr[PBLOCKS];
// bf16 split planes
__device__ __nv_bfloat16 g_wH[(size_t)WROWS*Hc];
__device__ __nv_bfloat16 g_wL[(size_t)WROWS*Hc];
__device__ __nv_bfloat16 g_eH[(size_t)Vc*Hc];
__device__ __nv_bfloat16 g_eL[(size_t)Vc*Hc];
__device__ __nv_bfloat16 g_mH[(size_t)2*TB*Hc];   // [dir][t*Bc+b][Hc]
__device__ __nv_bfloat16 g_mL[(size_t)2*TB*Hc];

__device__ __forceinline__ float sigf(float x) { return 1.f / (1.f + expf(-x)); }

// =================== mma.sync core =========================================
__device__ __forceinline__ uint32_t s2u(const void* p) {
    uint32_t a;
    asm("{ .reg .u64 t; cvta.to.shared.u64 t, %1; cvt.u32.u64 %0, t; }" : "=r"(a) : "l"(p));
    return a;
}
__device__ __forceinline__ void ldsm4(uint32_t& r0, uint32_t& r1, uint32_t& r2, uint32_t& r3, uint32_t a) {
    asm volatile("ldmatrix.sync.aligned.m8n8.x4.shared.b16 {%0,%1,%2,%3}, [%4];"
        : "=r"(r0), "=r"(r1), "=r"(r2), "=r"(r3) : "r"(a));
}
__device__ __forceinline__ void mma16816(float* d,
    uint32_t a0, uint32_t a1, uint32_t a2, uint32_t a3, uint32_t b0, uint32_t b1) {
    asm volatile("mma.sync.aligned.m16n8k16.row.col.f32.bf16.bf16.f32 "
        "{%0,%1,%2,%3}, {%4,%5,%6,%7}, {%8,%9}, {%0,%1,%2,%3};"
        : "+f"(d[0]), "+f"(d[1]), "+f"(d[2]), "+f"(d[3])
        : "r"(a0), "r"(a1), "r"(a2), "r"(a3), "r"(b0), "r"(b1));
}
__device__ __forceinline__ void pass_mma(uint32_t aAddr, uint32_t bAddr, float acc[2][4][4]) {
    uint32_t b0, b1, b2, b3, b4, b5, b6, b7;
    ldsm4(b0, b1, b2, b3, bAddr);
    ldsm4(b4, b5, b6, b7, bAddr + 1280);
#pragma unroll
    for (int mf = 0; mf < 2; mf++) {
        uint32_t a0, a1, a2, a3;
        ldsm4(a0, a1, a2, a3, aAddr + mf * 1280);
        mma16816(acc[mf][0], a0, a1, a2, a3, b0, b1);
        mma16816(acc[mf][1], a0, a1, a2, a3, b2, b3);
        mma16816(acc[mf][2], a0, a1, a2, a3, b4, b5);
        mma16816(acc[mf][3], a0, a1, a2, a3, b6, b7);
    }
}
// load-hoisted fused 3-product pass (8 ldsm then 24 mma) — 1 CTA/SM kernels
__device__ __forceinline__ void pass3(uint32_t ah, uint32_t al, uint32_t bh, uint32_t bl,
                                      float acc[2][4][4]) {
    uint32_t h0,h1,h2,h3,h4,h5,h6,h7, l0,l1,l2,l3,l4,l5,l6,l7;
    ldsm4(h0,h1,h2,h3, bh); ldsm4(h4,h5,h6,h7, bh + 1280);
    ldsm4(l0,l1,l2,l3, bl); ldsm4(l4,l5,l6,l7, bl + 1280);
#pragma unroll
    for (int mf = 0; mf < 2; mf++) {
        uint32_t a0,a1,a2,a3, c0,c1,c2,c3;
        ldsm4(a0,a1,a2,a3, ah + mf * 1280);
        ldsm4(c0,c1,c2,c3, al + mf * 1280);
        mma16816(acc[mf][0], a0,a1,a2,a3, h0,h1);
        mma16816(acc[mf][1], a0,a1,a2,a3, h2,h3);
        mma16816(acc[mf][2], a0,a1,a2,a3, h4,h5);
        mma16816(acc[mf][3], a0,a1,a2,a3, h6,h7);
        mma16816(acc[mf][0], a0,a1,a2,a3, l0,l1);
        mma16816(acc[mf][1], a0,a1,a2,a3, l2,l3);
        mma16816(acc[mf][2], a0,a1,a2,a3, l4,l5);
        mma16816(acc[mf][3], a0,a1,a2,a3, l6,l7);
        mma16816(acc[mf][0], c0,c1,c2,c3, h0,h1);
        mma16816(acc[mf][1], c0,c1,c2,c3, h2,h3);
        mma16816(acc[mf][2], c0,c1,c2,c3, h4,h5);
        mma16816(acc[mf][3], c0,c1,c2,c3, h6,h7);
    }
}
// 16-col-strip fused 3-product pass for the 512-thread scan (6 ldsm, 12 mma)
__device__ __forceinline__ void pass3_16(uint32_t ah, uint32_t al, uint32_t bh, uint32_t bl,
                                         float acc[2][2][4]) {
    uint32_t h0,h1,h2,h3, l0,l1,l2,l3;
    ldsm4(h0,h1,h2,h3, bh);
    ldsm4(l0,l1,l2,l3, bl);
#pragma unroll
    for (int mf = 0; mf < 2; mf++) {
        uint32_t a0,a1,a2,a3, c0,c1,c2,c3;
        ldsm4(a0,a1,a2,a3, ah + mf * 1280);
        ldsm4(c0,c1,c2,c3, al + mf * 1280);
        mma16816(acc[mf][0], a0,a1,a2,a3, h0,h1);
        mma16816(acc[mf][1], a0,a1,a2,a3, h2,h3);
        mma16816(acc[mf][0], a0,a1,a2,a3, l0,l1);
        mma16816(acc[mf][1], a0,a1,a2,a3, l2,l3);
        mma16816(acc[mf][0], c0,c1,c2,c3, h0,h1);
        mma16816(acc[mf][1], c0,c1,c2,c3, h2,h3);
    }
}
__device__ __forceinline__ uint32_t aLaneOff(int lane, int wm) {
    return (uint32_t)((lane & 15) * 80 + (lane >> 4) * 16 + wm * 2560);
}
__device__ __forceinline__ uint32_t bLaneOff(int lane, int wn) {
    return (uint32_t)((((lane & 7) + ((lane >> 4) & 1) * 8)) * 80 + ((lane >> 3) & 1) * 16 + wn * 2560);
}
__device__ __forceinline__ uint32_t packbf2(float a, float b) {
    __nv_bfloat162 v = __floats2bfloat162_rn(a, b);
    return *(uint32_t*)&v;
}
__device__ __forceinline__ float2 unpack2(uint32_t h, uint32_t l) {
    __nv_bfloat162 H = *(__nv_bfloat162*)&h, L = *(__nv_bfloat162*)&l;
    return make_float2(__bfloat162float(H.x) + __bfloat162float(L.x),
                       __bfloat162float(H.y) + __bfloat162float(L.y));
}
// ---- cp.async helpers ----
__device__ __forceinline__ void cpa16(uint32_t dst, const void* src) {
    asm volatile("cp.async.cg.shared.global [%0], [%1], 16;" :: "r"(dst), "l"(src));
}
#define CPC()  asm volatile("cp.async.commit_group;" ::: "memory")
#define CPW(n) asm volatile("cp.async.wait_group %0;" :: "n"(n) : "memory")

// ------------- split/convert kernels ---------------------------------------
__global__ void k_split_w(const float* __restrict__ Wz, const float* __restrict__ Wh,
                          const float* __restrict__ Wr, const float* __restrict__ Ur,
                          const float* __restrict__ U_w, const float* __restrict__ W_w,
                          const float* __restrict__ Wo_w)
{
    int r = blockIdx.x, c = threadIdx.x;
    float v;
    if      (r < 256)  v = Wz[r * 512 + c];
    else if (r < 512)  v = Wh[(r - 256) * 512 + c];
    else if (r < 768)  v = Wr[(r - 512) * 256 + c];
    else if (r < 1024) v = U_w[(r - 768) * 576 + c];
    else if (r < 1280) v = W_w[(r - 1024) * 320 + c];
    else if (r < 1536) v = U_w[(r - 1280) * 576 + 256 + c];
    else if (r < 2432) { int w = r - 1536; v = (w < Vc) ? Wo_w[(size_t)w * 256 + c] : 0.f; }
    else if (r < 2688) v = Wz[(r - 2432) * 512 + 256 + c];
    else if (r < 2944) v = Wh[(r - 2688) * 512 + 256 + c];
    else               v = Ur[(r - 2944) * 256 + c];
    __nv_bfloat16 h = __float2bfloat16(v);
    g_wH[(size_t)r * 256 + c] = h;
    g_wL[(size_t)r * 256 + c] = __float2bfloat16(v - __bfloat162float(h));
}

__global__ void k_split_emb(const float* __restrict__ emb)
{
    int r = blockIdx.x, c = threadIdx.x;
    float v = emb[(size_t)r * 256 + c];
    __nv_bfloat16 h = __float2bfloat16(v);
    g_eH[(size_t)r * 256 + c] = h;
    g_eL[(size_t)r * 256 + c] = __float2bfloat16(v - __bfloat162float(h));
}

// ------------- big GEMM: CTA 128x128, 512 threads, 16 warps ---------------
// warp (wm = warp>>2, wn = warp&3) -> 32x32 tile. A staged only twice per
// row panel (2 col-blocks) instead of 4x. Double-buffered cp.async.
#define TCG_ABUF 0        /* 2 x 20480: per slot [H 10240 | L 10240] */
#define TCG_BBUF 40960    /* 2 x 20480 */
#define TCG_DSM  81920
__global__ void __launch_bounds__(512) k_tcg(int modeBase, const int* __restrict__ wid,
                      const float* __restrict__ bz, const float* __restrict__ bh,
                      const float* __restrict__ br)
{
    extern __shared__ char smc[];
    uint32_t smb = s2u(smc);
    int tid = threadIdx.x, lane = tid & 31, warp = tid >> 5;   // 0..15
    int wm = warp >> 2, wn = warp & 3;
    int mode = modeBase + blockIdx.z;
    int rowBase = blockIdx.x * 128, colBase = blockIdx.y * 128;

    int wbase; float* outp; const float* bias;
    switch (mode) {
        case 0: wbase = 0;    outp = g_Az;  bias = bz; break;
        case 1: wbase = 256;  outp = g_Ah;  bias = bh; break;
        case 2: wbase = 512;  outp = g_Ar;  bias = br; break;
        case 3: wbase = 768;  outp = g_Px;  bias = 0;  break;
        case 4: wbase = 1024; outp = g_Pq;  bias = 0;  break;
        case 5: wbase = 1280; outp = g_Pmf; bias = 0;  break;
        default: wbase = 1280; outp = g_Pmr; bias = 0; break;
    }

    // A: 1024 16B-units (2 planes x 128 rows x 4 q); 2 per thread
    const uint4* aPtr[2];
    uint32_t aStore[2];
#pragma unroll
    for (int j = 0; j < 2; j++) {
        int u = tid + j * 512;
        int pl = u >= 512;
        int uu = u - pl * 512;
        int row = uu >> 2, q = uu & 3;
        aStore[j] = (uint32_t)(pl * 10240 + row * 80 + q * 16);
        int rA = rowBase + row;
        if (mode < 4) {
            int d = rA >> 11, b = rA & 2047;
            int sr = wid[b * Dc + d];
            aPtr[j] = (const uint4*)((pl ? g_eL : g_eH) + (size_t)sr * 256 + q * 8);
        } else {
            size_t rs = (size_t)((mode == 6) ? TB : 0) + rA;
            aPtr[j] = (const uint4*)((pl ? g_mL : g_mH) + rs * 256 + q * 8);
        }
    }
    // B: 1024 units (2 planes x 128 weight rows x 4 q); 2 per thread
    const uint4* bPtr[2];
    uint32_t bStore[2];
#pragma unroll
    for (int j = 0; j < 2; j++) {
        int u = tid + j * 512;
        int pl = u >= 512;
        int uu = u - pl * 512;
        int row = uu >> 2, q = uu & 3;
        bStore[j] = (uint32_t)(pl * 10240 + row * 80 + q * 16);
        bPtr[j] = (const uint4*)((pl ? g_wL : g_wH)
                 + (size_t)(wbase + colBase + row) * 256 + q * 8);
    }

    uint32_t aOff = aLaneOff(lane, wm);   // wm in 0..3 -> within 10240 plane
    uint32_t bOff = bLaneOff(lane, wn);   // wn in 0..3
    float acc[2][4][4] = {};

    auto stage = [&](int kc) {
        uint32_t ao = smb + TCG_ABUF + (uint32_t)((kc & 1) * 20480);
        uint32_t bo = smb + TCG_BBUF + (uint32_t)((kc & 1) * 20480);
#pragma unroll
        for (int j = 0; j < 2; j++) {
            cpa16(ao + aStore[j], aPtr[j] + kc * 4);
            cpa16(bo + bStore[j], bPtr[j] + kc * 4);
        }
        CPC();
    };

    stage(0);
    for (int kc = 0; kc < 8; kc++) {
        if (kc < 7) { stage(kc + 1); CPW(1); }
        else        { CPW(0); }
        __syncthreads();
        uint32_t ao = smb + TCG_ABUF + (uint32_t)((kc & 1) * 20480);
        uint32_t bo = smb + TCG_BBUF + (uint32_t)((kc & 1) * 20480);
#pragma unroll
        for (int kk = 0; kk < 2; kk++) {
            uint32_t kb = kk * 32;
            pass3(ao + aOff + kb, ao + 10240 + aOff + kb,
                  bo + bOff + kb, bo + 10240 + bOff + kb, acc);
        }
        __syncthreads();
    }

    // staged coalesced epilogue (reuses dead buffers; 16 warps x 4224 B)
    float* stg = (float*)smc + warp * (32 * 33);
#pragma unroll
    for (int mf = 0; mf < 2; mf++)
#pragma unroll
        for (int nf = 0; nf < 4; nf++) {
            int r = mf * 16 + (lane >> 2);
            int c = nf * 8 + ((lane & 3) << 1);
            stg[r * 33 + c]           = acc[mf][nf][0];
            stg[r * 33 + c + 1]       = acc[mf][nf][1];
            stg[(r + 8) * 33 + c]     = acc[mf][nf][2];
            stg[(r + 8) * 33 + c + 1] = acc[mf][nf][3];
        }
    __syncwarp();
    int colg = colBase + wn * 32 + lane;
    float bval = bias ? bias[colg] : 0.f;
#pragma unroll 8
    for (int r = 0; r < 32; r++) {
        int rowg = rowBase + wm * 32 + r;
        outp[(size_t)rowg * 256 + colg] = stg[r * 33 + lane] + bval;
    }
}

// ------------- tree_vec small GEMMs ----------------------------------------
__global__ void k_tree(const float* __restrict__ tv,
                       const float* __restrict__ W_w, const float* __restrict__ W_b,
                       const float* __restrict__ U_w, const float* __restrict__ U_b)
{
    int b = blockIdx.x, z = blockIdx.y, n = threadIdx.x;
    __shared__ float s_tv[Lc];
    if (n < Lc) s_tv[n] = tv[(size_t)b * Lc + n];
    __syncthreads();
    const float* W; int ld, koff; const float* bias; float* out;
    if (z == 0) { W = W_w; ld = Hc + Lc;   koff = Hc;   bias = W_b; out = g_Tq; }
    else        { W = U_w; ld = 2*Hc + Lc; koff = 2*Hc; bias = U_b; out = g_Tp; }
    const float* wr = W + (size_t)n * ld + koff;
    float s = bias[n];
#pragma unroll
    for (int k = 0; k < Lc; k += 4) {
        float4 w4 = *(const float4*)(wr + k);
        s += s_tv[k]*w4.x + s_tv[k+1]*w4.y + s_tv[k+2]*w4.z + s_tv[k+3]*w4.w;
    }
    out[(size_t)b * Hc + n] = s;
}

// ------------- fused row-local scan (R11-proven: 512 threads) --------------
// 128 CTAs: dir = bid>>6, rows rb..rb+31, all 256 cols.
// 16 warps: warp wn covers cols wn*16..+15 (one ldsm4 per B plane).
#define SC_MRES  0          /* 40960 */
#define SC_RMRES 40960      /* 40960 */
#define SC_BBUF  81920      /* 2 x 40960: per buf [H 20480 | L 20480] */
#define SC_AZ    163840     /* 32768 fp32 32x256 */
#define SC_AH    196608     /* 32768 */
#define SC_DSM   229376
__global__ void __launch_bounds__(512, 1) k_scan()
{
    extern __shared__ char smc[];
    uint32_t smb = s2u(smc);
    int tid = threadIdx.x, lane = tid & 31, warp = tid >> 5;  // warp 0..15
    int wn = warp;
    int dir = blockIdx.x >> 6;
    int rb = (blockIdx.x & 63) * 32;

    uint32_t aOff = aLaneOff(lane, 0);
    uint32_t bOff = (uint32_t)((((lane & 7) + ((lane >> 4) & 1) * 8)) * 80
                  + ((lane >> 3) & 1) * 16 + wn * 1280);

    for (int t = 0; t < Tc; t++) {
        int srcd = dir ? (Tc - t) : t;
        float accz[2][2][4] = {}, acch[2][2][4] = {};

        if (t > 0) {
            // -------- GEMM1: accz = m(t-1) @ Uz^T --------
            auto stage1 = [&](int kc) {
                uint32_t bo = smb + SC_BBUF + (uint32_t)((kc & 1) * 40960);
#pragma unroll
                for (int i = 0; i < 4; i++) {
                    int u = tid + i * 512;          // 0..2047
                    int pl = u >= 1024;
                    int uu = u - pl * 1024;
                    int col = uu >> 2, q = uu & 3;
                    const __nv_bfloat16* src = (pl ? g_wL : g_wH) + (size_t)(2432 + col) * 256 + kc * 32 + q * 8;
                    cpa16(bo + pl * 20480 + col * 80 + q * 16, src);
                }
                CPC();
            };
            stage1(0);
            for (int kc = 0; kc < 8; kc++) {
                if (kc < 7) { stage1(kc + 1); CPW(1); }
                else        { CPW(0); }
                __syncthreads();
                uint32_t bo = smb + SC_BBUF + (uint32_t)((kc & 1) * 40960);
                uint32_t aH = smb + SC_MRES + kc * 5120 + aOff;
#pragma unroll
                for (int kk = 0; kk < 2; kk++) {
                    uint32_t kb = kk * 32;
                    pass3_16(aH + kb, aH + 2560 + kb,
                             bo + bOff + kb, bo + 20480 + bOff + kb, accz);
                }
                __syncthreads();
            }
            // -------- GEMM2: acch = rm @ Uh^T  (+ Az/Ah slices) --------
            auto stage2 = [&](int kc) {
                uint32_t bo = smb + SC_BBUF + (uint32_t)((kc & 1) * 40960);
#pragma unroll
                for (int i = 0; i < 4; i++) {
                    int u = tid + i * 512;
                    int pl = u >= 1024;
                    int uu = u - pl * 1024;
                    int col = uu >> 2, q = uu & 3;
                    const __nv_bfloat16* src = (pl ? g_wL : g_wH) + (size_t)(2688 + col) * 256 + kc * 32 + q * 8;
                    cpa16(bo + pl * 20480 + col * 80 + q * 16, src);
                }
                {
                    int arr = tid >> 8;                   // 0: Az, 1: Ah
                    int g = kc * 256 + (tid & 255);       // 0..2047
                    int row = g >> 6, c16 = g & 63;
                    const float* src = (arr ? g_Ah : g_Az) + ((size_t)srcd * Bc + rb + row) * 256 + c16 * 4;
                    cpa16(smb + (arr ? SC_AH : SC_AZ) + row * 1024 + c16 * 16, src);
                }
                CPC();
            };
            stage2(0);
            for (int kc = 0; kc < 8; kc++) {
                if (kc < 7) { stage2(kc + 1); CPW(1); }
                else        { CPW(0); }
                __syncthreads();
                uint32_t bo = smb + SC_BBUF + (uint32_t)((kc & 1) * 40960);
                uint32_t aH = smb + SC_RMRES + kc * 5120 + aOff;
#pragma unroll
                for (int kk = 0; kk < 2; kk++) {
                    uint32_t kb = kk * 32;
                    pass3_16(aH + kb, aH + 2560 + kb,
                             bo + bOff + kb, bo + 20480 + bOff + kb, acch);
                }
                __syncthreads();
            }
        } else {
            // t == 0: only prefetch Az/Ah (4096 16B units over 512 threads)
#pragma unroll
            for (int i = 0; i < 8; i++) {
                int g = tid + i * 512;
                int arr = g >> 11;
                int gg = g & 2047;
                int row = gg >> 6, c16 = gg & 63;
                const float* src = (arr ? g_Ah : g_Az) + ((size_t)srcd * Bc + rb + row) * 256 + c16 * 4;
                cpa16(smb + (arr ? SC_AH : SC_AZ) + row * 1024 + c16 * 16, src);
            }
            CPC(); CPW(0);
            __syncthreads();
        }

        // -------- phase A epilogue: GRU update, write m to smem + global ----
        size_t gRowBase = (size_t)dir * TB + (size_t)t * Bc + rb;
#pragma unroll
        for (int mf = 0; mf < 2; mf++)
#pragma unroll
            for (int nf = 0; nf < 2; nf++) {
#pragma unroll
                for (int h = 0; h < 2; h++) {
                    int row = mf * 16 + (lane >> 2) + h * 8;
                    int col = wn * 16 + nf * 8 + ((lane & 3) << 1);
                    float2 az = *(const float2*)(smc + SC_AZ + row * 1024 + col * 4);
                    float2 ah = *(const float2*)(smc + SC_AH + row * 1024 + col * 4);
                    int chunk = col >> 5, k = col & 31, q = k >> 3, byo = (k & 7) * 2;
                    uint32_t mo = SC_MRES + chunk * 5120 + row * 80 + q * 16 + byo;
                    float2 mp = make_float2(0.f, 0.f);
                    if (t > 0)
                        mp = unpack2(*(uint32_t*)(smc + mo), *(uint32_t*)(smc + mo + 2560));
                    float z0 = sigf(accz[mf][nf][h*2+0] + az.x);
                    float z1 = sigf(accz[mf][nf][h*2+1] + az.y);
                    float q0 = tanhf(acch[mf][nf][h*2+0] + ah.x);
                    float q1 = tanhf(acch[mf][nf][h*2+1] + ah.y);
                    float m0 = (1.f - z0) * mp.x + z0 * q0;
                    float m1 = (1.f - z1) * mp.y + z1 * q1;
                    __nv_bfloat16 h0 = __float2bfloat16(m0), h1 = __float2bfloat16(m1);
                    uint32_t hv = packbf2(__bfloat162float(h0), __bfloat162float(h1));
                    uint32_t lv = packbf2(m0 - __bfloat162float(h0), m1 - __bfloat162float(h1));
                    *(uint32_t*)(smc + mo) = hv;
                    *(uint32_t*)(smc + mo + 2560) = lv;
                    size_t po = (gRowBase + row) * 256 + col;
                    *(uint32_t*)(g_mH + po) = hv;
                    *(uint32_t*)(g_mL + po) = lv;
                }
            }
        __syncthreads();

        if (t == Tc - 1) break;

        // -------- phase B: acc = m(t) @ Ur^T; rm = sigmoid(acc+Ar)*m -------
        {
            int dstd = dir ? (Tc - 1 - t) : (t + 1);
            float acc[2][2][4] = {};
            auto stage3 = [&](int kc) {
                uint32_t bo = smb + SC_BBUF + (uint32_t)((kc & 1) * 40960);
#pragma unroll
                for (int i = 0; i < 4; i++) {
                    int u = tid + i * 512;
                    int pl = u >= 1024;
                    int uu = u - pl * 1024;
                    int col = uu >> 2, q = uu & 3;
                    const __nv_bfloat16* src = (pl ? g_wL : g_wH) + (size_t)(2944 + col) * 256 + kc * 32 + q * 8;
                    cpa16(bo + pl * 20480 + col * 80 + q * 16, src);
                }
                if (tid < 256) {
                    int g = kc * 256 + tid;
                    int row = g >> 6, c16 = g & 63;
                    const float* src = g_Ar + ((size_t)dstd * Bc + rb + row) * 256 + c16 * 4;
                    cpa16(smb + SC_AZ + row * 1024 + c16 * 16, src);
                }
                CPC();
            };
            stage3(0);
            for (int kc = 0; kc < 8; kc++) {
                if (kc < 7) { stage3(kc + 1); CPW(1); }
                else        { CPW(0); }
                __syncthreads();
                uint32_t bo = smb + SC_BBUF + (uint32_t)((kc & 1) * 40960);
                uint32_t aH = smb + SC_MRES + kc * 5120 + aOff;
#pragma unroll
                for (int kk = 0; kk < 2; kk++) {
                    uint32_t kb = kk * 32;
                    pass3_16(aH + kb, aH + 2560 + kb,
                             bo + bOff + kb, bo + 20480 + bOff + kb, acc);
                }
                __syncthreads();
            }
#pragma unroll
            for (int mf = 0; mf < 2; mf++)
#pragma unroll
                for (int nf = 0; nf < 2; nf++) {
#pragma unroll
                    for (int h = 0; h < 2; h++) {
                        int row = mf * 16 + (lane >> 2) + h * 8;
                        int col = wn * 16 + nf * 8 + ((lane & 3) << 1);
                        float2 ar = *(const float2*)(smc + SC_AZ + row * 1024 + col * 4);
                        int chunk = col >> 5, k = col & 31, q = k >> 3, byo = (k & 7) * 2;
                        uint32_t mo = SC_MRES + chunk * 5120 + row * 80 + q * 16 + byo;
                        float2 mc = unpack2(*(uint32_t*)(smc + mo), *(uint32_t*)(smc + mo + 2560));
                        float r0 = sigf(acc[mf][nf][h*2+0] + ar.x);
                        float r1 = sigf(acc[mf][nf][h*2+1] + ar.y);
                        float rm0 = r0 * mc.x, rm1 = r1 * mc.y;
                        __nv_bfloat16 h0 = __float2bfloat16(rm0), h1 = __float2bfloat16(rm1);
                        uint32_t ro = SC_RMRES + chunk * 5120 + row * 80 + q * 16 + byo;
                        *(uint32_t*)(smc + ro) = packbf2(__bfloat162float(h0), __bfloat162float(h1));
                        *(uint32_t*)(smc + ro + 2560) = packbf2(rm0 - __bfloat162float(h0), rm1 - __bfloat162float(h1));
                    }
                }
            __syncthreads();
        }
    }
}

// ------------- fused q-head ------------------------------------------------
#define QH_B0   163840
#define QH_STG  184320
#define QH_BIAS 217600
#define QH_RED  217856
#define QH_DSM  218880
__global__ void k_qhead(const int* __restrict__ wid, const float* __restrict__ Wob)
{
    extern __shared__ char smc[];
    uint32_t smb = s2u(smc);
    int tid = threadIdx.x, lane = tid & 31, warp = tid >> 5;
    int wm = warp >> 1, wn = warp & 1;
    int rowBase = blockIdx.x * 128;

    for (int it = 0; it < 16; it++) {
        int idx = tid + it * 256;
        int row = idx >> 5, rem = idx & 31, kc = rem >> 2, q = rem & 3;
        int rA = rowBase + row, d = rA >> 11, b = rA & 2047;
        int k0 = kc * 32 + q * 8;
        const float4* tq = (const float4*)(g_Tq + (size_t)b * 256 + k0);
        float4 v0 = tq[0], v1 = tq[1];
        if (d) {
            const float4* pq = (const float4*)(g_Pq + ((size_t)(d - 1) * Bc + b) * 256 + k0);
            float4 p0 = pq[0], p1 = pq[1];
            v0.x += p0.x; v0.y += p0.y; v0.z += p0.z; v0.w += p0.w;
            v1.x += p1.x; v1.y += p1.y; v1.z += p1.z; v1.w += p1.w;
        }
        float vv[8] = { fmaxf(v0.x,0.f), fmaxf(v0.y,0.f), fmaxf(v0.z,0.f), fmaxf(v0.w,0.f),
                        fmaxf(v1.x,0.f), fmaxf(v1.y,0.f), fmaxf(v1.z,0.f), fmaxf(v1.w,0.f) };
        union { uint4 u; __nv_bfloat16 b8[8]; } Hx, Lx;
#pragma unroll
        for (int e = 0; e < 8; e++) {
            Hx.b8[e] = __float2bfloat16(vv[e]);
            Lx.b8[e] = __float2bfloat16(vv[e] - __bfloat162float(Hx.b8[e]));
        }
        uint32_t off = (uint32_t)(kc * 10240 + row * 80 + q * 16);
        *(uint4*)(smc + off) = Hx.u;
        *(uint4*)(smc + 81920 + off) = Lx.u;
    }
    __syncthreads();

    int myrow = tid >> 1, half = tid & 1;
    int rA0 = rowBase + myrow;
    int tgt = wid[(rA0 & 2047) * Dc + (rA0 >> 11)];
    float runMax = -3.4e38f, runSum = 0.f, sel = 0.f;
    int runIdx = Vc;

    uint32_t aOff = aLaneOff(lane, wm), bOff = bLaneOff(lane, wn);
    int bRow = tid >> 2, bQ = tid & 3;
    uint32_t bStore = (uint32_t)(bRow * 80 + bQ * 16);
    float* stg = (float*)(smc + QH_STG);
    float* s_bias = (float*)(smc + QH_BIAS);

    for (int cb = 0; cb < 13; cb++) {
        if (tid < 64) {
            int colg = cb * 64 + tid;
            s_bias[tid] = (colg < Vc) ? Wob[colg] : 0.f;
        }
        float acc[2][4][4] = {};
        const uint4* bh = (const uint4*)(g_wH + (size_t)(1536 + cb * 64 + bRow) * 256 + bQ * 8);
        const uint4* bl = (const uint4*)(g_wL + (size_t)(1536 + cb * 64 + bRow) * 256 + bQ * 8);
        auto stageB = [&](int kc) {
            uint32_t bo = smb + QH_B0 + (uint32_t)((kc & 1) * 10240);
            cpa16(bo + bStore, bh + kc * 4);
            cpa16(bo + 5120 + bStore, bl + kc * 4);
            CPC();
        };
        stageB(0);
        for (int kc = 0; kc < 8; kc++) {
            if (kc < 7) { stageB(kc + 1); CPW(1); }
            else        { CPW(0); }
            __syncthreads();
            uint32_t bo = smb + QH_B0 + (uint32_t)((kc & 1) * 10240);
#pragma unroll
            for (int kk = 0; kk < 2; kk++) {
                uint32_t kb = kk * 32;
                pass_mma(smb + kc * 10240 + aOff + kb,         bo + bOff + kb, acc);
                pass_mma(smb + kc * 10240 + aOff + kb,         bo + 5120 + bOff + kb, acc);
                pass_mma(smb + 81920 + kc * 10240 + aOff + kb, bo + bOff + kb, acc);
            }
            __syncthreads();
        }
#pragma unroll
        for (int mf = 0; mf < 2; mf++)
#pragma unroll
            for (int nf = 0; nf < 4; nf++) {
                int r = wm * 32 + mf * 16 + (lane >> 2);
                int c = wn * 32 + nf * 8 + ((lane & 3) << 1);
                stg[r * 65 + c]           = acc[mf][nf][0];
                stg[r * 65 + c + 1]       = acc[mf][nf][1];
                stg[(r + 8) * 65 + c]     = acc[mf][nf][2];
                stg[(r + 8) * 65 + c + 1] = acc[mf][nf][3];
            }
        __syncthreads();
        int colBaseT = cb * 64 + half * 32;
#pragma unroll 8
        for (int j = 0; j < 32; j++) {
            int col = colBaseT + j;
            if (col < Vc) {
                float v = stg[myrow * 65 + half * 32 + j] + s_bias[half * 32 + j];
                if (v > runMax) {
                    runSum = runSum * expf(runMax - v) + 1.f;
                    runMax = v; runIdx = col;
                } else {
                    runSum += expf(v - runMax);
                }
                if (col == tgt) sel = v;
            }
        }
        __syncthreads();
    }

    float oMax = __shfl_xor_sync(0xffffffffu, runMax, 1);
    float oSum = __shfl_xor_sync(0xffffffffu, runSum, 1);
    float oSel = __shfl_xor_sync(0xffffffffu, sel, 1);
    int   oIdx = __shfl_xor_sync(0xffffffffu, runIdx, 1);
    float M = fmaxf(runMax, oMax);
    float S = runSum * expf(runMax - M) + oSum * expf(oMax - M);
    int I = (oMax > runMax || (oMax == runMax && oIdx < runIdx)) ? oIdx : runIdx;
    float SEL = sel + oSel;

    float* lred = (float*)(smc + QH_RED);
    float* cred = lred + 128;
    if (half == 0) {
        lred[myrow] = (M + logf(S)) - SEL;
        cred[myrow] = (I == tgt) ? 1.f : 0.f;
    }
    __syncthreads();
    for (int o = 64; o; o >>= 1) {
        if (tid < o) { lred[tid] += lred[tid + o]; cred[tid] += cred[tid + o]; }
        __syncthreads();
    }
    if (tid == 0) {
        g_qpart_loss[blockIdx.x] = lred[0];
        g_qpart_corr[blockIdx.x] = cred[0];
    }
}

// ------------- p-head ------------------------------------------------------
__global__ void k_p(const float* __restrict__ usw, const float* __restrict__ usb)
{
    int warp = threadIdx.x >> 5, lane = threadIdx.x & 31;
    int row = blockIdx.x * 8 + warp;
    int s = row >> 11, b = row & (Bc - 1);

    int xd, c1, c2;
    if (s == 0)       { xd = 0; c1 = -1; c2 = -1; }
    else if (s <= Tc) { xd = s; c1 = s - 1; c2 = -1; }
    else { int j = s - (Tc + 1); xd = Tc - 1 - j; c1 = (j <= Tc - 2) ? (Tc - 2 - j) : -1; c2 = j; }

    const float* px = g_Px + ((size_t)xd * Bc + b) * Hc;
    const float* tp = g_Tp + (size_t)b * Hc;
    const float* f1 = (c1 >= 0) ? (g_Pmf + ((size_t)c1 * Bc + b) * Hc) : (const float*)0;
    const float* f2 = (c2 >= 0) ? (g_Pmr + ((size_t)c2 * Bc + b) * Hc) : (const float*)0;

    float acc = 0.f;
#pragma unroll
    for (int i = 0; i < 2; i++) {
        int n = (lane + 32 * i) * 4;
        float4 v = *(const float4*)(px + n);
        float4 t4 = *(const float4*)(tp + n);
        v.x += t4.x; v.y += t4.y; v.z += t4.z; v.w += t4.w;
        if (f1) { float4 a4 = *(const float4*)(f1 + n); v.x+=a4.x; v.y+=a4.y; v.z+=a4.z; v.w+=a4.w; }
        if (f2) { float4 a4 = *(const float4*)(f2 + n); v.x+=a4.x; v.y+=a4.y; v.z+=a4.z; v.w+=a4.w; }
        v.x = fmaxf(v.x,0.f); v.y = fmaxf(v.y,0.f); v.z = fmaxf(v.z,0.f); v.w = fmaxf(v.w,0.f);
        float4 u = *(const float4*)(usw + n);
        acc += v.x*u.x + v.y*u.y + v.z*u.z + v.w*u.w;
    }
#pragma unroll
    for (int o = 16; o; o >>= 1) acc += __shfl_xor_sync(0xffffffffu, acc, o);

    __shared__ float sl[8], sc[8];
    if (lane == 0) {
        float p = acc + usb[0];
        int tchk = (s < Tc) ? 1 : 0;
        float loss = fmaxf(p, 0.f) - (tchk ? p : 0.f) + log1pf(expf(-fabsf(p)));
        float corr = (((p > 0.f) ? 1 : 0) == tchk) ? 1.f : 0.f;
        sl[warp] = loss; sc[warp] = corr;
    }
    __syncthreads();
    if (threadIdx.x == 0) {
        float a = 0.f, c = 0.f;
        for (int w = 0; w < 8; w++) { a += sl[w]; c += sc[w]; }
        g_ppart_loss[blockIdx.x] = a;
        g_ppart_corr[blockIdx.x] = c;
    }
}

__global__ void k_finalize(float* __restrict__ out)
{
    __shared__ float sq[256], sqc[256], sp[256], spc[256];
    int t = threadIdx.x;
    float a = 0.f, b = 0.f, c = 0.f, d = 0.f;
    for (int i = t; i < QP; i += 256) { a += g_qpart_loss[i]; b += g_qpart_corr[i]; }
    for (int i = t; i < PBLOCKS; i += 256) { c += g_ppart_loss[i]; d += g_ppart_corr[i]; }
    sq[t] = a; sqc[t] = b; sp[t] = c; spc[t] = d;
    __syncthreads();
    for (int o = 128; o; o >>= 1) {
        if (t < o) { sq[t]+=sq[t+o]; sqc[t]+=sqc[t+o]; sp[t]+=sp[t+o]; spc[t]+=spc[t+o]; }
        __syncthreads();
    }
    if (t == 0) {
        out[0] = sq[0]  / (float)Bc;
        out[1] = sp[0]  / (float)Bc;
        out[2] = sqc[0] / (float)DB;
        out[3] = spc[0] / (float)SB;
    }
}

// ---------------------------------------------------------------------------
extern "C" void kernel_launch(void* const* d_in, const int* in_sizes, int n_in,
                              void* d_out, int out_size)
{
    const int*   wid      = (const int*)  d_in[0];
    const float* tree_vec = (const float*)d_in[1];
    const float* emb      = (const float*)d_in[2];
    const float* Wz       = (const float*)d_in[3];
    const float* bz       = (const float*)d_in[4];
    const float* Wr       = (const float*)d_in[5];
    const float* Ur       = (const float*)d_in[6];
    const float* br       = (const float*)d_in[7];
    const float* Wh       = (const float*)d_in[8];
    const float* bh       = (const float*)d_in[9];
    const float* W_w      = (const float*)d_in[10];
    const float* W_b      = (const float*)d_in[11];
    const float* U_w      = (const float*)d_in[12];
    const float* U_b      = (const float*)d_in[13];
    const float* Wo_w     = (const float*)d_in[14];
    const float* Wo_b     = (const float*)d_in[15];
    const float* Us_w     = (const float*)d_in[16];
    const float* Us_b     = (const float*)d_in[17];
    float* out = (float*)d_out;

    cudaFuncSetAttribute(k_tcg,   cudaFuncAttributeMaxDynamicSharedMemorySize, TCG_DSM);
    cudaFuncSetAttribute(k_scan,  cudaFuncAttributeMaxDynamicSharedMemorySize, SC_DSM);
    cudaFuncSetAttribute(k_qhead, cudaFuncAttributeMaxDynamicSharedMemorySize, QH_DSM);

    k_split_w<<<WROWS, 256>>>(Wz, Wh, Wr, Ur, U_w, W_w, Wo_w);
    k_split_emb<<<Vc, 256>>>(emb);
    k_tree<<<dim3(Bc, 2), 256>>>(tree_vec, W_w, W_b, U_w, U_b);

    k_tcg<<<dim3(DB/128, 2, 4), 512, TCG_DSM>>>(0, wid, bz, bh, br);

    k_scan<<<128, 512, SC_DSM>>>();

    k_tcg<<<dim3(TB/128, 2, 3), 512, TCG_DSM>>>(4, wid, bz, bh, br);
    k_qhead<<<DB/128, 256, QH_DSM>>>(wid, Wo_b);

    k_p<<<PBLOCKS, 256>>>(Us_w, Us_b);
    k_finalize<<<1, 256>>>(out);
}

// round 15
// speedup vs baseline: 1.3913x; 1.0262x over previous
#include <cuda_runtime.h>
#include <cuda_bf16.h>
#include <math.h>
#include <stdint.h>

#define Bc 2048
#define Dc 24
#define Hc 256
#define Lc 64
#define Vc 780
#define Tc 23
#define Sc 47
#define DB (Dc*Bc)
#define TB (Tc*Bc)
#define SB (Sc*Bc)
#define QP (DB/128)
#define PBLOCKS (SB/8)
#define WROWS 3200

// ---------------- fp32 scratch ---------------------------------------------
__device__ float g_Az[DB*Hc];
__device__ float g_Ah[DB*Hc];
__device__ float g_Ar[DB*Hc];
__device__ float g_Px[DB*Hc];
__device__ float g_Pq [TB*Hc];
__device__ float g_Pmf[TB*Hc];
__device__ float g_Pmr[TB*Hc];
__device__ float g_Tq[Bc*Hc];
__device__ float g_Tp[Bc*Hc];
__device__ float g_qpart_loss[QP];
__device__ float g_qpart_corr[QP];
__device__ float g_ppart_loss[PBLOCKS];
__device__ float g_ppart_corr[PBLOCKS];
// bf16 split planes
__device__ __nv_bfloat16 g_wH[(size_t)WROWS*Hc];
__device__ __nv_bfloat16 g_wL[(size_t)WROWS*Hc];
__device__ __nv_bfloat16 g_eH[(size_t)Vc*Hc];
__device__ __nv_bfloat16 g_eL[(size_t)Vc*Hc];
__device__ __nv_bfloat16 g_mH[(size_t)2*TB*Hc];   // [dir][t*Bc+b][Hc]
__device__ __nv_bfloat16 g_mL[(size_t)2*TB*Hc];

__device__ __forceinline__ float sigf(float x) { return 1.f / (1.f + expf(-x)); }

// =================== mma.sync core =========================================
__device__ __forceinline__ uint32_t s2u(const void* p) {
    uint32_t a;
    asm("{ .reg .u64 t; cvta.to.shared.u64 t, %1; cvt.u32.u64 %0, t; }" : "=r"(a) : "l"(p));
    return a;
}
__device__ __forceinline__ void ldsm4(uint32_t& r0, uint32_t& r1, uint32_t& r2, uint32_t& r3, uint32_t a) {
    asm volatile("ldmatrix.sync.aligned.m8n8.x4.shared.b16 {%0,%1,%2,%3}, [%4];"
        : "=r"(r0), "=r"(r1), "=r"(r2), "=r"(r3) : "r"(a));
}
__device__ __forceinline__ void mma16816(float* d,
    uint32_t a0, uint32_t a1, uint32_t a2, uint32_t a3, uint32_t b0, uint32_t b1) {
    asm volatile("mma.sync.aligned.m16n8k16.row.col.f32.bf16.bf16.f32 "
        "{%0,%1,%2,%3}, {%4,%5,%6,%7}, {%8,%9}, {%0,%1,%2,%3};"
        : "+f"(d[0]), "+f"(d[1]), "+f"(d[2]), "+f"(d[3])
        : "r"(a0), "r"(a1), "r"(a2), "r"(a3), "r"(b0), "r"(b1));
}
__device__ __forceinline__ void pass_mma(uint32_t aAddr, uint32_t bAddr, float acc[2][4][4]) {
    uint32_t b0, b1, b2, b3, b4, b5, b6, b7;
    ldsm4(b0, b1, b2, b3, bAddr);
    ldsm4(b4, b5, b6, b7, bAddr + 1280);
#pragma unroll
    for (int mf = 0; mf < 2; mf++) {
        uint32_t a0, a1, a2, a3;
        ldsm4(a0, a1, a2, a3, aAddr + mf * 1280);
        mma16816(acc[mf][0], a0, a1, a2, a3, b0, b1);
        mma16816(acc[mf][1], a0, a1, a2, a3, b2, b3);
        mma16816(acc[mf][2], a0, a1, a2, a3, b4, b5);
        mma16816(acc[mf][3], a0, a1, a2, a3, b6, b7);
    }
}
// load-hoisted fused 3-product pass (8 ldsm then 24 mma) — 1 CTA/SM kernels only
__device__ __forceinline__ void pass3(uint32_t ah, uint32_t al, uint32_t bh, uint32_t bl,
                                      float acc[2][4][4]) {
    uint32_t h0,h1,h2,h3,h4,h5,h6,h7, l0,l1,l2,l3,l4,l5,l6,l7;
    ldsm4(h0,h1,h2,h3, bh); ldsm4(h4,h5,h6,h7, bh + 1280);
    ldsm4(l0,l1,l2,l3, bl); ldsm4(l4,l5,l6,l7, bl + 1280);
#pragma unroll
    for (int mf = 0; mf < 2; mf++) {
        uint32_t a0,a1,a2,a3, c0,c1,c2,c3;
        ldsm4(a0,a1,a2,a3, ah + mf * 1280);
        ldsm4(c0,c1,c2,c3, al + mf * 1280);
        mma16816(acc[mf][0], a0,a1,a2,a3, h0,h1);
        mma16816(acc[mf][1], a0,a1,a2,a3, h2,h3);
        mma16816(acc[mf][2], a0,a1,a2,a3, h4,h5);
        mma16816(acc[mf][3], a0,a1,a2,a3, h6,h7);
        mma16816(acc[mf][0], a0,a1,a2,a3, l0,l1);
        mma16816(acc[mf][1], a0,a1,a2,a3, l2,l3);
        mma16816(acc[mf][2], a0,a1,a2,a3, l4,l5);
        mma16816(acc[mf][3], a0,a1,a2,a3, l6,l7);
        mma16816(acc[mf][0], c0,c1,c2,c3, h0,h1);
        mma16816(acc[mf][1], c0,c1,c2,c3, h2,h3);
        mma16816(acc[mf][2], c0,c1,c2,c3, h4,h5);
        mma16816(acc[mf][3], c0,c1,c2,c3, h6,h7);
    }
}
// 16-col-strip fused 3-product pass for the 512-thread scan (6 ldsm, 12 mma)
__device__ __forceinline__ void pass3_16(uint32_t ah, uint32_t al, uint32_t bh, uint32_t bl,
                                         float acc[2][2][4]) {
    uint32_t h0,h1,h2,h3, l0,l1,l2,l3;
    ldsm4(h0,h1,h2,h3, bh);
    ldsm4(l0,l1,l2,l3, bl);
#pragma unroll
    for (int mf = 0; mf < 2; mf++) {
        uint32_t a0,a1,a2,a3, c0,c1,c2,c3;
        ldsm4(a0,a1,a2,a3, ah + mf * 1280);
        ldsm4(c0,c1,c2,c3, al + mf * 1280);
        mma16816(acc[mf][0], a0,a1,a2,a3, h0,h1);
        mma16816(acc[mf][1], a0,a1,a2,a3, h2,h3);
        mma16816(acc[mf][0], a0,a1,a2,a3, l0,l1);
        mma16816(acc[mf][1], a0,a1,a2,a3, l2,l3);
        mma16816(acc[mf][0], c0,c1,c2,c3, h0,h1);
        mma16816(acc[mf][1], c0,c1,c2,c3, h2,h3);
    }
}
__device__ __forceinline__ uint32_t aLaneOff(int lane, int wm) {
    return (uint32_t)((lane & 15) * 80 + (lane >> 4) * 16 + wm * 2560);
}
__device__ __forceinline__ uint32_t bLaneOff(int lane, int wn) {
    return (uint32_t)((((lane & 7) + ((lane >> 4) & 1) * 8)) * 80 + ((lane >> 3) & 1) * 16 + wn * 2560);
}
__device__ __forceinline__ uint32_t packbf2(float a, float b) {
    __nv_bfloat162 v = __floats2bfloat162_rn(a, b);
    return *(uint32_t*)&v;
}
__device__ __forceinline__ float2 unpack2(uint32_t h, uint32_t l) {
    __nv_bfloat162 H = *(__nv_bfloat162*)&h, L = *(__nv_bfloat162*)&l;
    return make_float2(__bfloat162float(H.x) + __bfloat162float(L.x),
                       __bfloat162float(H.y) + __bfloat162float(L.y));
}
// ---- cp.async helpers ----
__device__ __forceinline__ void cpa16(uint32_t dst, const void* src) {
    asm volatile("cp.async.cg.shared.global [%0], [%1], 16;" :: "r"(dst), "l"(src));
}
#define CPC()  asm volatile("cp.async.commit_group;" ::: "memory")
#define CPW(n) asm volatile("cp.async.wait_group %0;" :: "n"(n) : "memory")

// ------------- split/convert kernels ---------------------------------------
__global__ void k_split_w(const float* __restrict__ Wz, const float* __restrict__ Wh,
                          const float* __restrict__ Wr, const float* __restrict__ Ur,
                          const float* __restrict__ U_w, const float* __restrict__ W_w,
                          const float* __restrict__ Wo_w)
{
    int r = blockIdx.x, c = threadIdx.x;
    float v;
    if      (r < 256)  v = Wz[r * 512 + c];
    else if (r < 512)  v = Wh[(r - 256) * 512 + c];
    else if (r < 768)  v = Wr[(r - 512) * 256 + c];
    else if (r < 1024) v = U_w[(r - 768) * 576 + c];
    else if (r < 1280) v = W_w[(r - 1024) * 320 + c];
    else if (r < 1536) v = U_w[(r - 1280) * 576 + 256 + c];
    else if (r < 2432) { int w = r - 1536; v = (w < Vc) ? Wo_w[(size_t)w * 256 + c] : 0.f; }
    else if (r < 2688) v = Wz[(r - 2432) * 512 + 256 + c];
    else if (r < 2944) v = Wh[(r - 2688) * 512 + 256 + c];
    else               v = Ur[(r - 2944) * 256 + c];
    __nv_bfloat16 h = __float2bfloat16(v);
    g_wH[(size_t)r * 256 + c] = h;
    g_wL[(size_t)r * 256 + c] = __float2bfloat16(v - __bfloat162float(h));
}

__global__ void k_split_emb(const float* __restrict__ emb)
{
    int r = blockIdx.x, c = threadIdx.x;
    float v = emb[(size_t)r * 256 + c];
    __nv_bfloat16 h = __float2bfloat16(v);
    g_eH[(size_t)r * 256 + c] = h;
    g_eL[(size_t)r * 256 + c] = __float2bfloat16(v - __bfloat162float(h));
}

// ------------- generic big GEMM (HMMA, CTA 128x64, double-buffered) --------
#define TCG_BUF 30720
#define TCG_DSM 61440
__global__ void __launch_bounds__(256, 3) k_tcg(int modeBase, const int* __restrict__ wid,
                      const float* __restrict__ bz, const float* __restrict__ bh,
                      const float* __restrict__ br)
{
    extern __shared__ char smc[];
    uint32_t smb = s2u(smc);
    int tid = threadIdx.x, lane = tid & 31, warp = tid >> 5;
    int wm = warp >> 1, wn = warp & 1;
    int mode = modeBase + blockIdx.z;
    int rowBase = blockIdx.x * 128, colBase = blockIdx.y * 64;

    int wbase; float* outp; const float* bias;
    switch (mode) {
        case 0: wbase = 0;    outp = g_Az;  bias = bz; break;
        case 1: wbase = 256;  outp = g_Ah;  bias = bh; break;
        case 2: wbase = 512;  outp = g_Ar;  bias = br; break;
        case 3: wbase = 768;  outp = g_Px;  bias = 0;  break;
        case 4: wbase = 1024; outp = g_Pq;  bias = 0;  break;
        case 5: wbase = 1280; outp = g_Pmf; bias = 0;  break;
        default: wbase = 1280; outp = g_Pmr; bias = 0; break;
    }

    const uint4 *aHp[2], *aLp[2];
    uint32_t aStore[2];
#pragma unroll
    for (int j = 0; j < 2; j++) {
        int idx = tid + j * 256;
        int row = idx >> 2, q = idx & 3;
        aStore[j] = (uint32_t)(row * 80 + q * 16);
        int rA = rowBase + row;
        if (mode < 4) {
            int d = rA >> 11, b = rA & 2047;
            int sr = wid[b * Dc + d];
            aHp[j] = (const uint4*)(g_eH + (size_t)sr * 256 + q * 8);
            aLp[j] = (const uint4*)(g_eL + (size_t)sr * 256 + q * 8);
        } else {
            size_t rs = (size_t)((mode == 6) ? TB : 0) + rA;
            aHp[j] = (const uint4*)(g_mH + rs * 256 + q * 8);
            aLp[j] = (const uint4*)(g_mL + rs * 256 + q * 8);
        }
    }
    int bRow = tid >> 2, bQ = tid & 3;
    uint32_t bStore = (uint32_t)(bRow * 80 + bQ * 16);
    const uint4* bHp = (const uint4*)(g_wH + (size_t)(wbase + colBase + bRow) * 256 + bQ * 8);
    const uint4* bLp = (const uint4*)(g_wL + (size_t)(wbase + colBase + bRow) * 256 + bQ * 8);

    uint32_t aOff = aLaneOff(lane, wm), bOff = bLaneOff(lane, wn);
    float acc[2][4][4] = {};

    auto stage = [&](int kc) {
        uint32_t bo = smb + (uint32_t)((kc & 1) * TCG_BUF);
#pragma unroll
        for (int j = 0; j < 2; j++) {
            cpa16(bo + aStore[j],         aHp[j] + kc * 4);
            cpa16(bo + 10240 + aStore[j], aLp[j] + kc * 4);
        }
        cpa16(bo + 20480 + bStore, bHp + kc * 4);
        cpa16(bo + 25600 + bStore, bLp + kc * 4);
        CPC();
    };

    stage(0);
    for (int kc = 0; kc < 8; kc++) {
        if (kc < 7) { stage(kc + 1); CPW(1); }
        else        { CPW(0); }
        __syncthreads();
        uint32_t bo = smb + (uint32_t)((kc & 1) * TCG_BUF);
#pragma unroll
        for (int kk = 0; kk < 2; kk++) {
            uint32_t kb = kk * 32;
            pass_mma(bo + aOff + kb,         bo + 20480 + bOff + kb, acc);
            pass_mma(bo + aOff + kb,         bo + 25600 + bOff + kb, acc);
            pass_mma(bo + 10240 + aOff + kb, bo + 20480 + bOff + kb, acc);
        }
        __syncthreads();
    }

    float* stg = (float*)smc + warp * (32 * 33);
#pragma unroll
    for (int mf = 0; mf < 2; mf++)
#pragma unroll
        for (int nf = 0; nf < 4; nf++) {
            int r = mf * 16 + (lane >> 2);
            int c = nf * 8 + ((lane & 3) << 1);
            stg[r * 33 + c]           = acc[mf][nf][0];
            stg[r * 33 + c + 1]       = acc[mf][nf][1];
            stg[(r + 8) * 33 + c]     = acc[mf][nf][2];
            stg[(r + 8) * 33 + c + 1] = acc[mf][nf][3];
        }
    __syncwarp();
    int colg = colBase + wn * 32 + lane;
    float bval = bias ? bias[colg] : 0.f;
#pragma unroll 8
    for (int r = 0; r < 32; r++) {
        int rowg = rowBase + wm * 32 + r;
        outp[(size_t)rowg * 256 + colg] = stg[r * 33 + lane] + bval;
    }
}

// ------------- tree_vec small GEMMs ----------------------------------------
__global__ void k_tree(const float* __restrict__ tv,
                       const float* __restrict__ W_w, const float* __restrict__ W_b,
                       const float* __restrict__ U_w, const float* __restrict__ U_b)
{
    int b = blockIdx.x, z = blockIdx.y, n = threadIdx.x;
    __shared__ float s_tv[Lc];
    if (n < Lc) s_tv[n] = tv[(size_t)b * Lc + n];
    __syncthreads();
    const float* W; int ld, koff; const float* bias; float* out;
    if (z == 0) { W = W_w; ld = Hc + Lc;   koff = Hc;   bias = W_b; out = g_Tq; }
    else        { W = U_w; ld = 2*Hc + Lc; koff = 2*Hc; bias = U_b; out = g_Tp; }
    const float* wr = W + (size_t)n * ld + koff;
    float s = bias[n];
#pragma unroll
    for (int k = 0; k < Lc; k += 4) {
        float4 w4 = *(const float4*)(wr + k);
        s += s_tv[k]*w4.x + s_tv[k+1]*w4.y + s_tv[k+2]*w4.z + s_tv[k+3]*w4.w;
    }
    out[(size_t)b * Hc + n] = s;
}

// ------------- fused row-local scan (R11-proven: 512 threads) --------------
#define SC_MRES  0          /* 40960 */
#define SC_RMRES 40960      /* 40960 */
#define SC_BBUF  81920      /* 2 x 40960: per buf [H 20480 | L 20480] */
#define SC_AZ    163840     /* 32768 fp32 32x256 */
#define SC_AH    196608     /* 32768 */
#define SC_DSM   229376
__global__ void __launch_bounds__(512, 1) k_scan()
{
    extern __shared__ char smc[];
    uint32_t smb = s2u(smc);
    int tid = threadIdx.x, lane = tid & 31, warp = tid >> 5;  // warp 0..15
    int wn = warp;
    int dir = blockIdx.x >> 6;
    int rb = (blockIdx.x & 63) * 32;

    uint32_t aOff = aLaneOff(lane, 0);
    uint32_t bOff = (uint32_t)((((lane & 7) + ((lane >> 4) & 1) * 8)) * 80
                  + ((lane >> 3) & 1) * 16 + wn * 1280);

    for (int t = 0; t < Tc; t++) {
        int srcd = dir ? (Tc - t) : t;
        float accz[2][2][4] = {}, acch[2][2][4] = {};

        if (t > 0) {
            auto stage1 = [&](int kc) {
                uint32_t bo = smb + SC_BBUF + (uint32_t)((kc & 1) * 40960);
#pragma unroll
                for (int i = 0; i < 4; i++) {
                    int u = tid + i * 512;
                    int pl = u >= 1024;
                    int uu = u - pl * 1024;
                    int col = uu >> 2, q = uu & 3;
                    const __nv_bfloat16* src = (pl ? g_wL : g_wH) + (size_t)(2432 + col) * 256 + kc * 32 + q * 8;
                    cpa16(bo + pl * 20480 + col * 80 + q * 16, src);
                }
                CPC();
            };
            stage1(0);
            for (int kc = 0; kc < 8; kc++) {
                if (kc < 7) { stage1(kc + 1); CPW(1); }
                else        { CPW(0); }
                __syncthreads();
                uint32_t bo = smb + SC_BBUF + (uint32_t)((kc & 1) * 40960);
                uint32_t aH = smb + SC_MRES + kc * 5120 + aOff;
#pragma unroll
                for (int kk = 0; kk < 2; kk++) {
                    uint32_t kb = kk * 32;
                    pass3_16(aH + kb, aH + 2560 + kb,
                             bo + bOff + kb, bo + 20480 + bOff + kb, accz);
                }
                __syncthreads();
            }
            auto stage2 = [&](int kc) {
                uint32_t bo = smb + SC_BBUF + (uint32_t)((kc & 1) * 40960);
#pragma unroll
                for (int i = 0; i < 4; i++) {
                    int u = tid + i * 512;
                    int pl = u >= 1024;
                    int uu = u - pl * 1024;
                    int col = uu >> 2, q = uu & 3;
                    const __nv_bfloat16* src = (pl ? g_wL : g_wH) + (size_t)(2688 + col) * 256 + kc * 32 + q * 8;
                    cpa16(bo + pl * 20480 + col * 80 + q * 16, src);
                }
                {
                    int arr = tid >> 8;
                    int g = kc * 256 + (tid & 255);
                    int row = g >> 6, c16 = g & 63;
                    const float* src = (arr ? g_Ah : g_Az) + ((size_t)srcd * Bc + rb + row) * 256 + c16 * 4;
                    cpa16(smb + (arr ? SC_AH : SC_AZ) + row * 1024 + c16 * 16, src);
                }
                CPC();
            };
            stage2(0);
            for (int kc = 0; kc < 8; kc++) {
                if (kc < 7) { stage2(kc + 1); CPW(1); }
                else        { CPW(0); }
                __syncthreads();
                uint32_t bo = smb + SC_BBUF + (uint32_t)((kc & 1) * 40960);
                uint32_t aH = smb + SC_RMRES + kc * 5120 + aOff;
#pragma unroll
                for (int kk = 0; kk < 2; kk++) {
                    uint32_t kb = kk * 32;
                    pass3_16(aH + kb, aH + 2560 + kb,
                             bo + bOff + kb, bo + 20480 + bOff + kb, acch);
                }
                __syncthreads();
            }
        } else {
#pragma unroll
            for (int i = 0; i < 8; i++) {
                int g = tid + i * 512;
                int arr = g >> 11;
                int gg = g & 2047;
                int row = gg >> 6, c16 = gg & 63;
                const float* src = (arr ? g_Ah : g_Az) + ((size_t)srcd * Bc + rb + row) * 256 + c16 * 4;
                cpa16(smb + (arr ? SC_AH : SC_AZ) + row * 1024 + c16 * 16, src);
            }
            CPC(); CPW(0);
            __syncthreads();
        }

        size_t gRowBase = (size_t)dir * TB + (size_t)t * Bc + rb;
#pragma unroll
        for (int mf = 0; mf < 2; mf++)
#pragma unroll
            for (int nf = 0; nf < 2; nf++) {
#pragma unroll
                for (int h = 0; h < 2; h++) {
                    int row = mf * 16 + (lane >> 2) + h * 8;
                    int col = wn * 16 + nf * 8 + ((lane & 3) << 1);
                    float2 az = *(const float2*)(smc + SC_AZ + row * 1024 + col * 4);
                    float2 ah = *(const float2*)(smc + SC_AH + row * 1024 + col * 4);
                    int chunk = col >> 5, k = col & 31, q = k >> 3, byo = (k & 7) * 2;
                    uint32_t mo = SC_MRES + chunk * 5120 + row * 80 + q * 16 + byo;
                    float2 mp = make_float2(0.f, 0.f);
                    if (t > 0)
                        mp = unpack2(*(uint32_t*)(smc + mo), *(uint32_t*)(smc + mo + 2560));
                    float z0 = sigf(accz[mf][nf][h*2+0] + az.x);
                    float z1 = sigf(accz[mf][nf][h*2+1] + az.y);
                    float q0 = tanhf(acch[mf][nf][h*2+0] + ah.x);
                    float q1 = tanhf(acch[mf][nf][h*2+1] + ah.y);
                    float m0 = (1.f - z0) * mp.x + z0 * q0;
                    float m1 = (1.f - z1) * mp.y + z1 * q1;
                    __nv_bfloat16 h0 = __float2bfloat16(m0), h1 = __float2bfloat16(m1);
                    uint32_t hv = packbf2(__bfloat162float(h0), __bfloat162float(h1));
                    uint32_t lv = packbf2(m0 - __bfloat162float(h0), m1 - __bfloat162float(h1));
                    *(uint32_t*)(smc + mo) = hv;
                    *(uint32_t*)(smc + mo + 2560) = lv;
                    size_t po = (gRowBase + row) * 256 + col;
                    *(uint32_t*)(g_mH + po) = hv;
                    *(uint32_t*)(g_mL + po) = lv;
                }
            }
        __syncthreads();

        if (t == Tc - 1) break;

        {
            int dstd = dir ? (Tc - 1 - t) : (t + 1);
            float acc[2][2][4] = {};
            auto stage3 = [&](int kc) {
                uint32_t bo = smb + SC_BBUF + (uint32_t)((kc & 1) * 40960);
#pragma unroll
                for (int i = 0; i < 4; i++) {
                    int u = tid + i * 512;
                    int pl = u >= 1024;
                    int uu = u - pl * 1024;
                    int col = uu >> 2, q = uu & 3;
                    const __nv_bfloat16* src = (pl ? g_wL : g_wH) + (size_t)(2944 + col) * 256 + kc * 32 + q * 8;
                    cpa16(bo + pl * 20480 + col * 80 + q * 16, src);
                }
                if (tid < 256) {
                    int g = kc * 256 + tid;
                    int row = g >> 6, c16 = g & 63;
                    const float* src = g_Ar + ((size_t)dstd * Bc + rb + row) * 256 + c16 * 4;
                    cpa16(smb + SC_AZ + row * 1024 + c16 * 16, src);
                }
                CPC();
            };
            stage3(0);
            for (int kc = 0; kc < 8; kc++) {
                if (kc < 7) { stage3(kc + 1); CPW(1); }
                else        { CPW(0); }
                __syncthreads();
                uint32_t bo = smb + SC_BBUF + (uint32_t)((kc & 1) * 40960);
                uint32_t aH = smb + SC_MRES + kc * 5120 + aOff;
#pragma unroll
                for (int kk = 0; kk < 2; kk++) {
                    uint32_t kb = kk * 32;
                    pass3_16(aH + kb, aH + 2560 + kb,
                             bo + bOff + kb, bo + 20480 + bOff + kb, acc);
                }
                __syncthreads();
            }
#pragma unroll
            for (int mf = 0; mf < 2; mf++)
#pragma unroll
                for (int nf = 0; nf < 2; nf++) {
#pragma unroll
                    for (int h = 0; h < 2; h++) {
                        int row = mf * 16 + (lane >> 2) + h * 8;
                        int col = wn * 16 + nf * 8 + ((lane & 3) << 1);
                        float2 ar = *(const float2*)(smc + SC_AZ + row * 1024 + col * 4);
                        int chunk = col >> 5, k = col & 31, q = k >> 3, byo = (k & 7) * 2;
                        uint32_t mo = SC_MRES + chunk * 5120 + row * 80 + q * 16 + byo;
                        float2 mc = unpack2(*(uint32_t*)(smc + mo), *(uint32_t*)(smc + mo + 2560));
                        float r0 = sigf(acc[mf][nf][h*2+0] + ar.x);
                        float r1 = sigf(acc[mf][nf][h*2+1] + ar.y);
                        float rm0 = r0 * mc.x, rm1 = r1 * mc.y;
                        __nv_bfloat16 h0 = __float2bfloat16(rm0), h1 = __float2bfloat16(rm1);
                        uint32_t ro = SC_RMRES + chunk * 5120 + row * 80 + q * 16 + byo;
                        *(uint32_t*)(smc + ro) = packbf2(__bfloat162float(h0), __bfloat162float(h1));
                        *(uint32_t*)(smc + ro + 2560) = packbf2(rm0 - __bfloat162float(h0), rm1 - __bfloat162float(h1));
                    }
                }
            __syncthreads();
        }
    }
}

// ------------- fused q-head ------------------------------------------------
#define QH_B0   163840
#define QH_STG  184320
#define QH_BIAS 217600
#define QH_RED  217856
#define QH_DSM  218880
__global__ void k_qhead(const int* __restrict__ wid, const float* __restrict__ Wob)
{
    extern __shared__ char smc[];
    uint32_t smb = s2u(smc);
    int tid = threadIdx.x, lane = tid & 31, warp = tid >> 5;
    int wm = warp >> 1, wn = warp & 1;
    int rowBase = blockIdx.x * 128;

    for (int it = 0; it < 16; it++) {
        int idx = tid + it * 256;
        int row = idx >> 5, rem = idx & 31, kc = rem >> 2, q = rem & 3;
        int rA = rowBase + row, d = rA >> 11, b = rA & 2047;
        int k0 = kc * 32 + q * 8;
        const float4* tq = (const float4*)(g_Tq + (size_t)b * 256 + k0);
        float4 v0 = tq[0], v1 = tq[1];
        if (d) {
            const float4* pq = (const float4*)(g_Pq + ((size_t)(d - 1) * Bc + b) * 256 + k0);
            float4 p0 = pq[0], p1 = pq[1];
            v0.x += p0.x; v0.y += p0.y; v0.z += p0.z; v0.w += p0.w;
            v1.x += p1.x; v1.y += p1.y; v1.z += p1.z; v1.w += p1.w;
        }
        float vv[8] = { fmaxf(v0.x,0.f), fmaxf(v0.y,0.f), fmaxf(v0.z,0.f), fmaxf(v0.w,0.f),
                        fmaxf(v1.x,0.f), fmaxf(v1.y,0.f), fmaxf(v1.z,0.f), fmaxf(v1.w,0.f) };
        union { uint4 u; __nv_bfloat16 b8[8]; } Hx, Lx;
#pragma unroll
        for (int e = 0; e < 8; e++) {
            Hx.b8[e] = __float2bfloat16(vv[e]);
            Lx.b8[e] = __float2bfloat16(vv[e] - __bfloat162float(Hx.b8[e]));
        }
        uint32_t off = (uint32_t)(kc * 10240 + row * 80 + q * 16);
        *(uint4*)(smc + off) = Hx.u;
        *(uint4*)(smc + 81920 + off) = Lx.u;
    }
    __syncthreads();

    int myrow = tid >> 1, half = tid & 1;
    int rA0 = rowBase + myrow;
    int tgt = wid[(rA0 & 2047) * Dc + (rA0 >> 11)];
    float runMax = -3.4e38f, runSum = 0.f, sel = 0.f;
    int runIdx = Vc;

    uint32_t aOff = aLaneOff(lane, wm), bOff = bLaneOff(lane, wn);
    int bRow = tid >> 2, bQ = tid & 3;
    uint32_t bStore = (uint32_t)(bRow * 80 + bQ * 16);
    float* stg = (float*)(smc + QH_STG);
    float* s_bias = (float*)(smc + QH_BIAS);

    for (int cb = 0; cb < 13; cb++) {
        if (tid < 64) {
            int colg = cb * 64 + tid;
            s_bias[tid] = (colg < Vc) ? Wob[colg] : 0.f;
        }
        float acc[2][4][4] = {};
        const uint4* bh = (const uint4*)(g_wH + (size_t)(1536 + cb * 64 + bRow) * 256 + bQ * 8);
        const uint4* bl = (const uint4*)(g_wL + (size_t)(1536 + cb * 64 + bRow) * 256 + bQ * 8);
        auto stageB = [&](int kc) {
            uint32_t bo = smb + QH_B0 + (uint32_t)((kc & 1) * 10240);
            cpa16(bo + bStore, bh + kc * 4);
            cpa16(bo + 5120 + bStore, bl + kc * 4);
            CPC();
        };
        stageB(0);
        for (int kc = 0; kc < 8; kc++) {
            if (kc < 7) { stageB(kc + 1); CPW(1); }
            else        { CPW(0); }
            __syncthreads();
            uint32_t bo = smb + QH_B0 + (uint32_t)((kc & 1) * 10240);
#pragma unroll
            for (int kk = 0; kk < 2; kk++) {
                uint32_t kb = kk * 32;
                pass3(smb + kc * 10240 + aOff + kb,
                      smb + 81920 + kc * 10240 + aOff + kb,
                      bo + bOff + kb,
                      bo + 5120 + bOff + kb, acc);
            }
            __syncthreads();
        }
#pragma unroll
        for (int mf = 0; mf < 2; mf++)
#pragma unroll
            for (int nf = 0; nf < 4; nf++) {
                int r = wm * 32 + mf * 16 + (lane >> 2);
                int c = wn * 32 + nf * 8 + ((lane & 3) << 1);
                stg[r * 65 + c]           = acc[mf][nf][0];
                stg[r * 65 + c + 1]       = acc[mf][nf][1];
                stg[(r + 8) * 65 + c]     = acc[mf][nf][2];
                stg[(r + 8) * 65 + c + 1] = acc[mf][nf][3];
            }
        __syncthreads();
        int colBaseT = cb * 64 + half * 32;
#pragma unroll 8
        for (int j = 0; j < 32; j++) {
            int col = colBaseT + j;
            if (col < Vc) {
                float v = stg[myrow * 65 + half * 32 + j] + s_bias[half * 32 + j];
                if (v > runMax) {
                    runSum = runSum * expf(runMax - v) + 1.f;
                    runMax = v; runIdx = col;
                } else {
                    runSum += expf(v - runMax);
                }
                if (col == tgt) sel = v;
            }
        }
        __syncthreads();
    }

    float oMax = __shfl_xor_sync(0xffffffffu, runMax, 1);
    float oSum = __shfl_xor_sync(0xffffffffu, runSum, 1);
    float oSel = __shfl_xor_sync(0xffffffffu, sel, 1);
    int   oIdx = __shfl_xor_sync(0xffffffffu, runIdx, 1);
    float M = fmaxf(runMax, oMax);
    float S = runSum * expf(runMax - M) + oSum * expf(oMax - M);
    int I = (oMax > runMax || (oMax == runMax && oIdx < runIdx)) ? oIdx : runIdx;
    float SEL = sel + oSel;

    float* lred = (float*)(smc + QH_RED);
    float* cred = lred + 128;
    if (half == 0) {
        lred[myrow] = (M + logf(S)) - SEL;
        cred[myrow] = (I == tgt) ? 1.f : 0.f;
    }
    __syncthreads();
    for (int o = 64; o; o >>= 1) {
        if (tid < o) { lred[tid] += lred[tid + o]; cred[tid] += cred[tid + o]; }
        __syncthreads();
    }
    if (tid == 0) {
        g_qpart_loss[blockIdx.x] = lred[0];
        g_qpart_corr[blockIdx.x] = cred[0];
    }
}

// ------------- p-head ------------------------------------------------------
__global__ void k_p(const float* __restrict__ usw, const float* __restrict__ usb)
{
    int warp = threadIdx.x >> 5, lane = threadIdx.x & 31;
    int row = blockIdx.x * 8 + warp;
    int s = row >> 11, b = row & (Bc - 1);

    int xd, c1, c2;
    if (s == 0)       { xd = 0; c1 = -1; c2 = -1; }
    else if (s <= Tc) { xd = s; c1 = s - 1; c2 = -1; }
    else { int j = s - (Tc + 1); xd = Tc - 1 - j; c1 = (j <= Tc - 2) ? (Tc - 2 - j) : -1; c2 = j; }

    const float* px = g_Px + ((size_t)xd * Bc + b) * Hc;
    const float* tp = g_Tp + (size_t)b * Hc;
    const float* f1 = (c1 >= 0) ? (g_Pmf + ((size_t)c1 * Bc + b) * Hc) : (const float*)0;
    const float* f2 = (c2 >= 0) ? (g_Pmr + ((size_t)c2 * Bc + b) * Hc) : (const float*)0;

    float acc = 0.f;
#pragma unroll
    for (int i = 0; i < 2; i++) {
        int n = (lane + 32 * i) * 4;
        float4 v = *(const float4*)(px + n);
        float4 t4 = *(const float4*)(tp + n);
        v.x += t4.x; v.y += t4.y; v.z += t4.z; v.w += t4.w;
        if (f1) { float4 a4 = *(const float4*)(f1 + n); v.x+=a4.x; v.y+=a4.y; v.z+=a4.z; v.w+=a4.w; }
        if (f2) { float4 a4 = *(const float4*)(f2 + n); v.x+=a4.x; v.y+=a4.y; v.z+=a4.z; v.w+=a4.w; }
        v.x = fmaxf(v.x,0.f); v.y = fmaxf(v.y,0.f); v.z = fmaxf(v.z,0.f); v.w = fmaxf(v.w,0.f);
        float4 u = *(const float4*)(usw + n);
        acc += v.x*u.x + v.y*u.y + v.z*u.z + v.w*u.w;
    }
#pragma unroll
    for (int o = 16; o; o >>= 1) acc += __shfl_xor_sync(0xffffffffu, acc, o);

    __shared__ float sl[8], sc[8];
    if (lane == 0) {
        float p = acc + usb[0];
        int tchk = (s < Tc) ? 1 : 0;
        float loss = fmaxf(p, 0.f) - (tchk ? p : 0.f) + log1pf(expf(-fabsf(p)));
        float corr = (((p > 0.f) ? 1 : 0) == tchk) ? 1.f : 0.f;
        sl[warp] = loss; sc[warp] = corr;
    }
    __syncthreads();
    if (threadIdx.x == 0) {
        float a = 0.f, c = 0.f;
        for (int w = 0; w < 8; w++) { a += sl[w]; c += sc[w]; }
        g_ppart_loss[blockIdx.x] = a;
        g_ppart_corr[blockIdx.x] = c;
    }
}

__global__ void k_finalize(float* __restrict__ out)
{
    __shared__ float sq[256], sqc[256], sp[256], spc[256];
    int t = threadIdx.x;
    float a = 0.f, b = 0.f, c = 0.f, d = 0.f;
    for (int i = t; i < QP; i += 256) { a += g_qpart_loss[i]; b += g_qpart_corr[i]; }
    for (int i = t; i < PBLOCKS; i += 256) { c += g_ppart_loss[i]; d += g_ppart_corr[i]; }
    sq[t] = a; sqc[t] = b; sp[t] = c; spc[t] = d;
    __syncthreads();
    for (int o = 128; o; o >>= 1) {
        if (t < o) { sq[t]+=sq[t+o]; sqc[t]+=sqc[t+o]; sp[t]+=sp[t+o]; spc[t]+=spc[t+o]; }
        __syncthreads();
    }
    if (t == 0) {
        out[0] = sq[0]  / (float)Bc;
        out[1] = sp[0]  / (float)Bc;
        out[2] = sqc[0] / (float)DB;
        out[3] = spc[0] / (float)SB;
    }
}

// ---------------------------------------------------------------------------
extern "C" void kernel_launch(void* const* d_in, const int* in_sizes, int n_in,
                              void* d_out, int out_size)
{
    const int*   wid      = (const int*)  d_in[0];
    const float* tree_vec = (const float*)d_in[1];
    const float* emb      = (const float*)d_in[2];
    const float* Wz       = (const float*)d_in[3];
    const float* bz       = (const float*)d_in[4];
    const float* Wr       = (const float*)d_in[5];
    const float* Ur       = (const float*)d_in[6];
    const float* br       = (const float*)d_in[7];
    const float* Wh       = (const float*)d_in[8];
    const float* bh       = (const float*)d_in[9];
    const float* W_w      = (const float*)d_in[10];
    const float* W_b      = (const float*)d_in[11];
    const float* U_w      = (const float*)d_in[12];
    const float* U_b      = (const float*)d_in[13];
    const float* Wo_w     = (const float*)d_in[14];
    const float* Wo_b     = (const float*)d_in[15];
    const float* Us_w     = (const float*)d_in[16];
    const float* Us_b     = (const float*)d_in[17];
    float* out = (float*)d_out;

    cudaFuncSetAttribute(k_tcg,   cudaFuncAttributeMaxDynamicSharedMemorySize, TCG_DSM);
    cudaFuncSetAttribute(k_scan,  cudaFuncAttributeMaxDynamicSharedMemorySize, SC_DSM);
    cudaFuncSetAttribute(k_qhead, cudaFuncAttributeMaxDynamicSharedMemorySize, QH_DSM);

    k_split_w<<<WROWS, 256>>>(Wz, Wh, Wr, Ur, U_w, W_w, Wo_w);
    k_split_emb<<<Vc, 256>>>(emb);
    k_tree<<<dim3(Bc, 2), 256>>>(tree_vec, W_w, W_b, U_w, U_b);

    k_tcg<<<dim3(DB/128, 4, 4), 256, TCG_DSM>>>(0, wid, bz, bh, br);

    k_scan<<<128, 512, SC_DSM>>>();

    k_tcg<<<dim3(TB/128, 4, 3), 256, TCG_DSM>>>(4, wid, bz, bh, br);
    k_qhead<<<DB/128, 256, QH_DSM>>>(wid, Wo_b);

    k_p<<<PBLOCKS, 256>>>(Us_w, Us_b);
    k_finalize<<<1, 256>>>(out);
}

// round 16
// speedup vs baseline: 1.3993x; 1.0058x over previous
#include <cuda_runtime.h>
#include <cuda_bf16.h>
#include <math.h>
#include <stdint.h>

#define Bc 2048
#define Dc 24
#define Hc 256
#define Lc 64
#define Vc 780
#define Tc 23
#define Sc 47
#define DB (Dc*Bc)
#define TB (Tc*Bc)
#define SB (Sc*Bc)
#define QP (DB/128)
#define PBLOCKS (SB/8)
#define WROWS 3200

// ---------------- fp32 scratch ---------------------------------------------
__device__ float g_Az[DB*Hc];
__device__ float g_Ah[DB*Hc];
__device__ float g_Ar[DB*Hc];
__device__ float g_Px[DB*Hc];
__device__ float g_Pq [TB*Hc];
__device__ float g_Pmf[TB*Hc];
__device__ float g_Pmr[TB*Hc];
__device__ float g_Tq[Bc*Hc];
__device__ float g_Tp[Bc*Hc];
__device__ float g_qpart_loss[QP];
__device__ float g_qpart_corr[QP];
__device__ float g_ppart_loss[PBLOCKS];
__device__ float g_ppart_corr[PBLOCKS];
// bf16 split planes
__device__ __nv_bfloat16 g_wH[(size_t)WROWS*Hc];
__device__ __nv_bfloat16 g_wL[(size_t)WROWS*Hc];
__device__ __nv_bfloat16 g_eH[(size_t)Vc*Hc];
__device__ __nv_bfloat16 g_eL[(size_t)Vc*Hc];
__device__ __nv_bfloat16 g_mH[(size_t)2*TB*Hc];   // [dir][t*Bc+b][Hc]
__device__ __nv_bfloat16 g_mL[(size_t)2*TB*Hc];

__device__ __forceinline__ float sigf(float x) { return 1.f / (1.f + expf(-x)); }

// =================== mma.sync core =========================================
__device__ __forceinline__ uint32_t s2u(const void* p) {
    uint32_t a;
    asm("{ .reg .u64 t; cvta.to.shared.u64 t, %1; cvt.u32.u64 %0, t; }" : "=r"(a) : "l"(p));
    return a;
}
__device__ __forceinline__ void ldsm4(uint32_t& r0, uint32_t& r1, uint32_t& r2, uint32_t& r3, uint32_t a) {
    asm volatile("ldmatrix.sync.aligned.m8n8.x4.shared.b16 {%0,%1,%2,%3}, [%4];"
        : "=r"(r0), "=r"(r1), "=r"(r2), "=r"(r3) : "r"(a));
}
__device__ __forceinline__ void mma16816(float* d,
    uint32_t a0, uint32_t a1, uint32_t a2, uint32_t a3, uint32_t b0, uint32_t b1) {
    asm volatile("mma.sync.aligned.m16n8k16.row.col.f32.bf16.bf16.f32 "
        "{%0,%1,%2,%3}, {%4,%5,%6,%7}, {%8,%9}, {%0,%1,%2,%3};"
        : "+f"(d[0]), "+f"(d[1]), "+f"(d[2]), "+f"(d[3])
        : "r"(a0), "r"(a1), "r"(a2), "r"(a3), "r"(b0), "r"(b1));
}
__device__ __forceinline__ void pass_mma(uint32_t aAddr, uint32_t bAddr, float acc[2][4][4]) {
    uint32_t b0, b1, b2, b3, b4, b5, b6, b7;
    ldsm4(b0, b1, b2, b3, bAddr);
    ldsm4(b4, b5, b6, b7, bAddr + 1280);
#pragma unroll
    for (int mf = 0; mf < 2; mf++) {
        uint32_t a0, a1, a2, a3;
        ldsm4(a0, a1, a2, a3, aAddr + mf * 1280);
        mma16816(acc[mf][0], a0, a1, a2, a3, b0, b1);
        mma16816(acc[mf][1], a0, a1, a2, a3, b2, b3);
        mma16816(acc[mf][2], a0, a1, a2, a3, b4, b5);
        mma16816(acc[mf][3], a0, a1, a2, a3, b6, b7);
    }
}
// load-hoisted fused 3-product pass (8 ldsm then 24 mma) — 1 CTA/SM kernels only
__device__ __forceinline__ void pass3(uint32_t ah, uint32_t al, uint32_t bh, uint32_t bl,
                                      float acc[2][4][4]) {
    uint32_t h0,h1,h2,h3,h4,h5,h6,h7, l0,l1,l2,l3,l4,l5,l6,l7;
    ldsm4(h0,h1,h2,h3, bh); ldsm4(h4,h5,h6,h7, bh + 1280);
    ldsm4(l0,l1,l2,l3, bl); ldsm4(l4,l5,l6,l7, bl + 1280);
#pragma unroll
    for (int mf = 0; mf < 2; mf++) {
        uint32_t a0,a1,a2,a3, c0,c1,c2,c3;
        ldsm4(a0,a1,a2,a3, ah + mf * 1280);
        ldsm4(c0,c1,c2,c3, al + mf * 1280);
        mma16816(acc[mf][0], a0,a1,a2,a3, h0,h1);
        mma16816(acc[mf][1], a0,a1,a2,a3, h2,h3);
        mma16816(acc[mf][2], a0,a1,a2,a3, h4,h5);
        mma16816(acc[mf][3], a0,a1,a2,a3, h6,h7);
        mma16816(acc[mf][0], a0,a1,a2,a3, l0,l1);
        mma16816(acc[mf][1], a0,a1,a2,a3, l2,l3);
        mma16816(acc[mf][2], a0,a1,a2,a3, l4,l5);
        mma16816(acc[mf][3], a0,a1,a2,a3, l6,l7);
        mma16816(acc[mf][0], c0,c1,c2,c3, h0,h1);
        mma16816(acc[mf][1], c0,c1,c2,c3, h2,h3);
        mma16816(acc[mf][2], c0,c1,c2,c3, h4,h5);
        mma16816(acc[mf][3], c0,c1,c2,c3, h6,h7);
    }
}
// 16-col-strip fused 3-product pass for the 512-thread scan (6 ldsm, 12 mma)
__device__ __forceinline__ void pass3_16(uint32_t ah, uint32_t al, uint32_t bh, uint32_t bl,
                                         float acc[2][2][4]) {
    uint32_t h0,h1,h2,h3, l0,l1,l2,l3;
    ldsm4(h0,h1,h2,h3, bh);
    ldsm4(l0,l1,l2,l3, bl);
#pragma unroll
    for (int mf = 0; mf < 2; mf++) {
        uint32_t a0,a1,a2,a3, c0,c1,c2,c3;
        ldsm4(a0,a1,a2,a3, ah + mf * 1280);
        ldsm4(c0,c1,c2,c3, al + mf * 1280);
        mma16816(acc[mf][0], a0,a1,a2,a3, h0,h1);
        mma16816(acc[mf][1], a0,a1,a2,a3, h2,h3);
        mma16816(acc[mf][0], a0,a1,a2,a3, l0,l1);
        mma16816(acc[mf][1], a0,a1,a2,a3, l2,l3);
        mma16816(acc[mf][0], c0,c1,c2,c3, h0,h1);
        mma16816(acc[mf][1], c0,c1,c2,c3, h2,h3);
    }
}
__device__ __forceinline__ uint32_t aLaneOff(int lane, int wm) {
    return (uint32_t)((lane & 15) * 80 + (lane >> 4) * 16 + wm * 2560);
}
__device__ __forceinline__ uint32_t bLaneOff(int lane, int wn) {
    return (uint32_t)((((lane & 7) + ((lane >> 4) & 1) * 8)) * 80 + ((lane >> 3) & 1) * 16 + wn * 2560);
}
__device__ __forceinline__ uint32_t packbf2(float a, float b) {
    __nv_bfloat162 v = __floats2bfloat162_rn(a, b);
    return *(uint32_t*)&v;
}
__device__ __forceinline__ float2 unpack2(uint32_t h, uint32_t l) {
    __nv_bfloat162 H = *(__nv_bfloat162*)&h, L = *(__nv_bfloat162*)&l;
    return make_float2(__bfloat162float(H.x) + __bfloat162float(L.x),
                       __bfloat162float(H.y) + __bfloat162float(L.y));
}
// ---- cp.async helpers ----
__device__ __forceinline__ void cpa16(uint32_t dst, const void* src) {
    asm volatile("cp.async.cg.shared.global [%0], [%1], 16;" :: "r"(dst), "l"(src));
}
#define CPC()  asm volatile("cp.async.commit_group;" ::: "memory")
#define CPW(n) asm volatile("cp.async.wait_group %0;" :: "n"(n) : "memory")

// ------------- split/convert kernels ---------------------------------------
__global__ void k_split_w(const float* __restrict__ Wz, const float* __restrict__ Wh,
                          const float* __restrict__ Wr, const float* __restrict__ Ur,
                          const float* __restrict__ U_w, const float* __restrict__ W_w,
                          const float* __restrict__ Wo_w)
{
    int r = blockIdx.x, c = threadIdx.x;
    float v;
    if      (r < 256)  v = Wz[r * 512 + c];
    else if (r < 512)  v = Wh[(r - 256) * 512 + c];
    else if (r < 768)  v = Wr[(r - 512) * 256 + c];
    else if (r < 1024) v = U_w[(r - 768) * 576 + c];
    else if (r < 1280) v = W_w[(r - 1024) * 320 + c];
    else if (r < 1536) v = U_w[(r - 1280) * 576 + 256 + c];
    else if (r < 2432) { int w = r - 1536; v = (w < Vc) ? Wo_w[(size_t)w * 256 + c] : 0.f; }
    else if (r < 2688) v = Wz[(r - 2432) * 512 + 256 + c];
    else if (r < 2944) v = Wh[(r - 2688) * 512 + 256 + c];
    else               v = Ur[(r - 2944) * 256 + c];
    __nv_bfloat16 h = __float2bfloat16(v);
    g_wH[(size_t)r * 256 + c] = h;
    g_wL[(size_t)r * 256 + c] = __float2bfloat16(v - __bfloat162float(h));
}

__global__ void k_split_emb(const float* __restrict__ emb)
{
    int r = blockIdx.x, c = threadIdx.x;
    float v = emb[(size_t)r * 256 + c];
    __nv_bfloat16 h = __float2bfloat16(v);
    g_eH[(size_t)r * 256 + c] = h;
    g_eL[(size_t)r * 256 + c] = __float2bfloat16(v - __bfloat162float(h));
}

// ------------- generic big GEMM (HMMA, CTA 128x64, double-buffered) --------
#define TCG_BUF 30720
#define TCG_DSM 61440
__global__ void __launch_bounds__(256, 3) k_tcg(int modeBase, const int* __restrict__ wid,
                      const float* __restrict__ bz, const float* __restrict__ bh,
                      const float* __restrict__ br)
{
    extern __shared__ char smc[];
    uint32_t smb = s2u(smc);
    int tid = threadIdx.x, lane = tid & 31, warp = tid >> 5;
    int wm = warp >> 1, wn = warp & 1;
    int mode = modeBase + blockIdx.z;
    int rowBase = blockIdx.x * 128, colBase = blockIdx.y * 64;

    int wbase; float* outp; const float* bias;
    switch (mode) {
        case 0: wbase = 0;    outp = g_Az;  bias = bz; break;
        case 1: wbase = 256;  outp = g_Ah;  bias = bh; break;
        case 2: wbase = 512;  outp = g_Ar;  bias = br; break;
        case 3: wbase = 768;  outp = g_Px;  bias = 0;  break;
        case 4: wbase = 1024; outp = g_Pq;  bias = 0;  break;
        case 5: wbase = 1280; outp = g_Pmf; bias = 0;  break;
        default: wbase = 1280; outp = g_Pmr; bias = 0; break;
    }

    const uint4 *aHp[2], *aLp[2];
    uint32_t aStore[2];
#pragma unroll
    for (int j = 0; j < 2; j++) {
        int idx = tid + j * 256;
        int row = idx >> 2, q = idx & 3;
        aStore[j] = (uint32_t)(row * 80 + q * 16);
        int rA = rowBase + row;
        if (mode < 4) {
            int d = rA >> 11, b = rA & 2047;
            int sr = wid[b * Dc + d];
            aHp[j] = (const uint4*)(g_eH + (size_t)sr * 256 + q * 8);
            aLp[j] = (const uint4*)(g_eL + (size_t)sr * 256 + q * 8);
        } else {
            size_t rs = (size_t)((mode == 6) ? TB : 0) + rA;
            aHp[j] = (const uint4*)(g_mH + rs * 256 + q * 8);
            aLp[j] = (const uint4*)(g_mL + rs * 256 + q * 8);
        }
    }
    int bRow = tid >> 2, bQ = tid & 3;
    uint32_t bStore = (uint32_t)(bRow * 80 + bQ * 16);
    const uint4* bHp = (const uint4*)(g_wH + (size_t)(wbase + colBase + bRow) * 256 + bQ * 8);
    const uint4* bLp = (const uint4*)(g_wL + (size_t)(wbase + colBase + bRow) * 256 + bQ * 8);

    uint32_t aOff = aLaneOff(lane, wm), bOff = bLaneOff(lane, wn);
    float acc[2][4][4] = {};

    auto stage = [&](int kc) {
        uint32_t bo = smb + (uint32_t)((kc & 1) * TCG_BUF);
#pragma unroll
        for (int j = 0; j < 2; j++) {
            cpa16(bo + aStore[j],         aHp[j] + kc * 4);
            cpa16(bo + 10240 + aStore[j], aLp[j] + kc * 4);
        }
        cpa16(bo + 20480 + bStore, bHp + kc * 4);
        cpa16(bo + 25600 + bStore, bLp + kc * 4);
        CPC();
    };

    stage(0);
    for (int kc = 0; kc < 8; kc++) {
        if (kc < 7) { stage(kc + 1); CPW(1); }
        else        { CPW(0); }
        __syncthreads();
        uint32_t bo = smb + (uint32_t)((kc & 1) * TCG_BUF);
#pragma unroll
        for (int kk = 0; kk < 2; kk++) {
            uint32_t kb = kk * 32;
            pass_mma(bo + aOff + kb,         bo + 20480 + bOff + kb, acc);
            pass_mma(bo + aOff + kb,         bo + 25600 + bOff + kb, acc);
            pass_mma(bo + 10240 + aOff + kb, bo + 20480 + bOff + kb, acc);
        }
        __syncthreads();
    }

    float* stg = (float*)smc + warp * (32 * 33);
#pragma unroll
    for (int mf = 0; mf < 2; mf++)
#pragma unroll
        for (int nf = 0; nf < 4; nf++) {
            int r = mf * 16 + (lane >> 2);
            int c = nf * 8 + ((lane & 3) << 1);
            stg[r * 33 + c]           = acc[mf][nf][0];
            stg[r * 33 + c + 1]       = acc[mf][nf][1];
            stg[(r + 8) * 33 + c]     = acc[mf][nf][2];
            stg[(r + 8) * 33 + c + 1] = acc[mf][nf][3];
        }
    __syncwarp();
    int colg = colBase + wn * 32 + lane;
    float bval = bias ? bias[colg] : 0.f;
#pragma unroll 8
    for (int r = 0; r < 32; r++) {
        int rowg = rowBase + wm * 32 + r;
        outp[(size_t)rowg * 256 + colg] = stg[r * 33 + lane] + bval;
    }
}

// ------------- tree_vec small GEMMs ----------------------------------------
__global__ void k_tree(const float* __restrict__ tv,
                       const float* __restrict__ W_w, const float* __restrict__ W_b,
                       const float* __restrict__ U_w, const float* __restrict__ U_b)
{
    int b = blockIdx.x, z = blockIdx.y, n = threadIdx.x;
    __shared__ float s_tv[Lc];
    if (n < Lc) s_tv[n] = tv[(size_t)b * Lc + n];
    __syncthreads();
    const float* W; int ld, koff; const float* bias; float* out;
    if (z == 0) { W = W_w; ld = Hc + Lc;   koff = Hc;   bias = W_b; out = g_Tq; }
    else        { W = U_w; ld = 2*Hc + Lc; koff = 2*Hc; bias = U_b; out = g_Tp; }
    const float* wr = W + (size_t)n * ld + koff;
    float s = bias[n];
#pragma unroll
    for (int k = 0; k < Lc; k += 4) {
        float4 w4 = *(const float4*)(wr + k);
        s += s_tv[k]*w4.x + s_tv[k+1]*w4.y + s_tv[k+2]*w4.z + s_tv[k+3]*w4.w;
    }
    out[(size_t)b * Hc + n] = s;
}

// ------------- fused row-local scan (R11-proven: 512 threads) --------------
#define SC_MRES  0          /* 40960 */
#define SC_RMRES 40960      /* 40960 */
#define SC_BBUF  81920      /* 2 x 40960: per buf [H 20480 | L 20480] */
#define SC_AZ    163840     /* 32768 fp32 32x256 */
#define SC_AH    196608     /* 32768 */
#define SC_DSM   229376
__global__ void __launch_bounds__(512, 1) k_scan()
{
    extern __shared__ char smc[];
    uint32_t smb = s2u(smc);
    int tid = threadIdx.x, lane = tid & 31, warp = tid >> 5;  // warp 0..15
    int wn = warp;
    int dir = blockIdx.x >> 6;
    int rb = (blockIdx.x & 63) * 32;

    uint32_t aOff = aLaneOff(lane, 0);
    uint32_t bOff = (uint32_t)((((lane & 7) + ((lane >> 4) & 1) * 8)) * 80
                  + ((lane >> 3) & 1) * 16 + wn * 1280);

    for (int t = 0; t < Tc; t++) {
        int srcd = dir ? (Tc - t) : t;
        float accz[2][2][4] = {}, acch[2][2][4] = {};

        if (t > 0) {
            auto stage1 = [&](int kc) {
                uint32_t bo = smb + SC_BBUF + (uint32_t)((kc & 1) * 40960);
#pragma unroll
                for (int i = 0; i < 4; i++) {
                    int u = tid + i * 512;
                    int pl = u >= 1024;
                    int uu = u - pl * 1024;
                    int col = uu >> 2, q = uu & 3;
                    const __nv_bfloat16* src = (pl ? g_wL : g_wH) + (size_t)(2432 + col) * 256 + kc * 32 + q * 8;
                    cpa16(bo + pl * 20480 + col * 80 + q * 16, src);
                }
                CPC();
            };
            stage1(0);
            for (int kc = 0; kc < 8; kc++) {
                if (kc < 7) { stage1(kc + 1); CPW(1); }
                else        { CPW(0); }
                __syncthreads();
                uint32_t bo = smb + SC_BBUF + (uint32_t)((kc & 1) * 40960);
                uint32_t aH = smb + SC_MRES + kc * 5120 + aOff;
#pragma unroll
                for (int kk = 0; kk < 2; kk++) {
                    uint32_t kb = kk * 32;
                    pass3_16(aH + kb, aH + 2560 + kb,
                             bo + bOff + kb, bo + 20480 + bOff + kb, accz);
                }
                __syncthreads();
            }
            auto stage2 = [&](int kc) {
                uint32_t bo = smb + SC_BBUF + (uint32_t)((kc & 1) * 40960);
#pragma unroll
                for (int i = 0; i < 4; i++) {
                    int u = tid + i * 512;
                    int pl = u >= 1024;
                    int uu = u - pl * 1024;
                    int col = uu >> 2, q = uu & 3;
                    const __nv_bfloat16* src = (pl ? g_wL : g_wH) + (size_t)(2688 + col) * 256 + kc * 32 + q * 8;
                    cpa16(bo + pl * 20480 + col * 80 + q * 16, src);
                }
                {
                    int arr = tid >> 8;
                    int g = kc * 256 + (tid & 255);
                    int row = g >> 6, c16 = g & 63;
                    const float* src = (arr ? g_Ah : g_Az) + ((size_t)srcd * Bc + rb + row) * 256 + c16 * 4;
                    cpa16(smb + (arr ? SC_AH : SC_AZ) + row * 1024 + c16 * 16, src);
                }
                CPC();
            };
            stage2(0);
            for (int kc = 0; kc < 8; kc++) {
                if (kc < 7) { stage2(kc + 1); CPW(1); }
                else        { CPW(0); }
                __syncthreads();
                uint32_t bo = smb + SC_BBUF + (uint32_t)((kc & 1) * 40960);
                uint32_t aH = smb + SC_RMRES + kc * 5120 + aOff;
#pragma unroll
                for (int kk = 0; kk < 2; kk++) {
                    uint32_t kb = kk * 32;
                    pass3_16(aH + kb, aH + 2560 + kb,
                             bo + bOff + kb, bo + 20480 + bOff + kb, acch);
                }
                __syncthreads();
            }
        } else {
#pragma unroll
            for (int i = 0; i < 8; i++) {
                int g = tid + i * 512;
                int arr = g >> 11;
                int gg = g & 2047;
                int row = gg >> 6, c16 = gg & 63;
                const float* src = (arr ? g_Ah : g_Az) + ((size_t)srcd * Bc + rb + row) * 256 + c16 * 4;
                cpa16(smb + (arr ? SC_AH : SC_AZ) + row * 1024 + c16 * 16, src);
            }
            CPC(); CPW(0);
            __syncthreads();
        }

        size_t gRowBase = (size_t)dir * TB + (size_t)t * Bc + rb;
#pragma unroll
        for (int mf = 0; mf < 2; mf++)
#pragma unroll
            for (int nf = 0; nf < 2; nf++) {
#pragma unroll
                for (int h = 0; h < 2; h++) {
                    int row = mf * 16 + (lane >> 2) + h * 8;
                    int col = wn * 16 + nf * 8 + ((lane & 3) << 1);
                    float2 az = *(const float2*)(smc + SC_AZ + row * 1024 + col * 4);
                    float2 ah = *(const float2*)(smc + SC_AH + row * 1024 + col * 4);
                    int chunk = col >> 5, k = col & 31, q = k >> 3, byo = (k & 7) * 2;
                    uint32_t mo = SC_MRES + chunk * 5120 + row * 80 + q * 16 + byo;
                    float2 mp = make_float2(0.f, 0.f);
                    if (t > 0)
                        mp = unpack2(*(uint32_t*)(smc + mo), *(uint32_t*)(smc + mo + 2560));
                    float z0 = sigf(accz[mf][nf][h*2+0] + az.x);
                    float z1 = sigf(accz[mf][nf][h*2+1] + az.y);
                    float q0 = tanhf(acch[mf][nf][h*2+0] + ah.x);
                    float q1 = tanhf(acch[mf][nf][h*2+1] + ah.y);
                    float m0 = (1.f - z0) * mp.x + z0 * q0;
                    float m1 = (1.f - z1) * mp.y + z1 * q1;
                    __nv_bfloat16 h0 = __float2bfloat16(m0), h1 = __float2bfloat16(m1);
                    uint32_t hv = packbf2(__bfloat162float(h0), __bfloat162float(h1));
                    uint32_t lv = packbf2(m0 - __bfloat162float(h0), m1 - __bfloat162float(h1));
                    *(uint32_t*)(smc + mo) = hv;
                    *(uint32_t*)(smc + mo + 2560) = lv;
                    size_t po = (gRowBase + row) * 256 + col;
                    *(uint32_t*)(g_mH + po) = hv;
                    *(uint32_t*)(g_mL + po) = lv;
                }
            }
        __syncthreads();

        if (t == Tc - 1) break;

        {
            int dstd = dir ? (Tc - 1 - t) : (t + 1);
            float acc[2][2][4] = {};
            auto stage3 = [&](int kc) {
                uint32_t bo = smb + SC_BBUF + (uint32_t)((kc & 1) * 40960);
#pragma unroll
                for (int i = 0; i < 4; i++) {
                    int u = tid + i * 512;
                    int pl = u >= 1024;
                    int uu = u - pl * 1024;
                    int col = uu >> 2, q = uu & 3;
                    const __nv_bfloat16* src = (pl ? g_wL : g_wH) + (size_t)(2944 + col) * 256 + kc * 32 + q * 8;
                    cpa16(bo + pl * 20480 + col * 80 + q * 16, src);
                }
                if (tid < 256) {
                    int g = kc * 256 + tid;
                    int row = g >> 6, c16 = g & 63;
                    const float* src = g_Ar + ((size_t)dstd * Bc + rb + row) * 256 + c16 * 4;
                    cpa16(smb + SC_AZ + row * 1024 + c16 * 16, src);
                }
                CPC();
            };
            stage3(0);
            for (int kc = 0; kc < 8; kc++) {
                if (kc < 7) { stage3(kc + 1); CPW(1); }
                else        { CPW(0); }
                __syncthreads();
                uint32_t bo = smb + SC_BBUF + (uint32_t)((kc & 1) * 40960);
                uint32_t aH = smb + SC_MRES + kc * 5120 + aOff;
#pragma unroll
                for (int kk = 0; kk < 2; kk++) {
                    uint32_t kb = kk * 32;
                    pass3_16(aH + kb, aH + 2560 + kb,
                             bo + bOff + kb, bo + 20480 + bOff + kb, acc);
                }
                __syncthreads();
            }
#pragma unroll
            for (int mf = 0; mf < 2; mf++)
#pragma unroll
                for (int nf = 0; nf < 2; nf++) {
#pragma unroll
                    for (int h = 0; h < 2; h++) {
                        int row = mf * 16 + (lane >> 2) + h * 8;
                        int col = wn * 16 + nf * 8 + ((lane & 3) << 1);
                        float2 ar = *(const float2*)(smc + SC_AZ + row * 1024 + col * 4);
                        int chunk = col >> 5, k = col & 31, q = k >> 3, byo = (k & 7) * 2;
                        uint32_t mo = SC_MRES + chunk * 5120 + row * 80 + q * 16 + byo;
                        float2 mc = unpack2(*(uint32_t*)(smc + mo), *(uint32_t*)(smc + mo + 2560));
                        float r0 = sigf(acc[mf][nf][h*2+0] + ar.x);
                        float r1 = sigf(acc[mf][nf][h*2+1] + ar.y);
                        float rm0 = r0 * mc.x, rm1 = r1 * mc.y;
                        __nv_bfloat16 h0 = __float2bfloat16(rm0), h1 = __float2bfloat16(rm1);
                        uint32_t ro = SC_RMRES + chunk * 5120 + row * 80 + q * 16 + byo;
                        *(uint32_t*)(smc + ro) = packbf2(__bfloat162float(h0), __bfloat162float(h1));
                        *(uint32_t*)(smc + ro + 2560) = packbf2(rm0 - __bfloat162float(h0), rm1 - __bfloat162float(h1));
                    }
                }
            __syncthreads();
        }
    }
}

// ------------- fused q-head ------------------------------------------------
#define QH_B0   163840
#define QH_STG  184320
#define QH_BIAS 217600
#define QH_RED  217856
#define QH_DSM  218880
__global__ void k_qhead(const int* __restrict__ wid, const float* __restrict__ Wob)
{
    extern __shared__ char smc[];
    uint32_t smb = s2u(smc);
    int tid = threadIdx.x, lane = tid & 31, warp = tid >> 5;
    int wm = warp >> 1, wn = warp & 1;
    int rowBase = blockIdx.x * 128;

    for (int it = 0; it < 16; it++) {
        int idx = tid + it * 256;
        int row = idx >> 5, rem = idx & 31, kc = rem >> 2, q = rem & 3;
        int rA = rowBase + row, d = rA >> 11, b = rA & 2047;
        int k0 = kc * 32 + q * 8;
        const float4* tq = (const float4*)(g_Tq + (size_t)b * 256 + k0);
        float4 v0 = tq[0], v1 = tq[1];
        if (d) {
            const float4* pq = (const float4*)(g_Pq + ((size_t)(d - 1) * Bc + b) * 256 + k0);
            float4 p0 = pq[0], p1 = pq[1];
            v0.x += p0.x; v0.y += p0.y; v0.z += p0.z; v0.w += p0.w;
            v1.x += p1.x; v1.y += p1.y; v1.z += p1.z; v1.w += p1.w;
        }
        float vv[8] = { fmaxf(v0.x,0.f), fmaxf(v0.y,0.f), fmaxf(v0.z,0.f), fmaxf(v0.w,0.f),
                        fmaxf(v1.x,0.f), fmaxf(v1.y,0.f), fmaxf(v1.z,0.f), fmaxf(v1.w,0.f) };
        union { uint4 u; __nv_bfloat16 b8[8]; } Hx, Lx;
#pragma unroll
        for (int e = 0; e < 8; e++) {
            Hx.b8[e] = __float2bfloat16(vv[e]);
            Lx.b8[e] = __float2bfloat16(vv[e] - __bfloat162float(Hx.b8[e]));
        }
        uint32_t off = (uint32_t)(kc * 10240 + row * 80 + q * 16);
        *(uint4*)(smc + off) = Hx.u;
        *(uint4*)(smc + 81920 + off) = Lx.u;
    }
    __syncthreads();

    int myrow = tid >> 1, half = tid & 1;
    int rA0 = rowBase + myrow;
    int tgt = wid[(rA0 & 2047) * Dc + (rA0 >> 11)];
    float runMax = -3.4e38f, runSum = 0.f, sel = 0.f;
    int runIdx = Vc;

    uint32_t aOff = aLaneOff(lane, wm), bOff = bLaneOff(lane, wn);
    int bRow = tid >> 2, bQ = tid & 3;
    uint32_t bStore = (uint32_t)(bRow * 80 + bQ * 16);
    float* stg = (float*)(smc + QH_STG);
    float* s_bias = (float*)(smc + QH_BIAS);

    for (int cb = 0; cb < 13; cb++) {
        if (tid < 64) {
            int colg = cb * 64 + tid;
            s_bias[tid] = (colg < Vc) ? Wob[colg] : 0.f;
        }
        float acc[2][4][4] = {};
        const uint4* bh = (const uint4*)(g_wH + (size_t)(1536 + cb * 64 + bRow) * 256 + bQ * 8);
        const uint4* bl = (const uint4*)(g_wL + (size_t)(1536 + cb * 64 + bRow) * 256 + bQ * 8);
        auto stageB = [&](int kc) {
            uint32_t bo = smb + QH_B0 + (uint32_t)((kc & 1) * 10240);
            cpa16(bo + bStore, bh + kc * 4);
            cpa16(bo + 5120 + bStore, bl + kc * 4);
            CPC();
        };
        stageB(0);
        for (int kc = 0; kc < 8; kc++) {
            if (kc < 7) { stageB(kc + 1); CPW(1); }
            else        { CPW(0); }
            __syncthreads();
            uint32_t bo = smb + QH_B0 + (uint32_t)((kc & 1) * 10240);
#pragma unroll
            for (int kk = 0; kk < 2; kk++) {
                uint32_t kb = kk * 32;
                pass3(smb + kc * 10240 + aOff + kb,
                      smb + 81920 + kc * 10240 + aOff + kb,
                      bo + bOff + kb,
                      bo + 5120 + bOff + kb, acc);
            }
            __syncthreads();
        }
#pragma unroll
        for (int mf = 0; mf < 2; mf++)
#pragma unroll
            for (int nf = 0; nf < 4; nf++) {
                int r = wm * 32 + mf * 16 + (lane >> 2);
                int c = wn * 32 + nf * 8 + ((lane & 3) << 1);
                stg[r * 65 + c]           = acc[mf][nf][0];
                stg[r * 65 + c + 1]       = acc[mf][nf][1];
                stg[(r + 8) * 65 + c]     = acc[mf][nf][2];
                stg[(r + 8) * 65 + c + 1] = acc[mf][nf][3];
            }
        __syncthreads();
        int colBaseT = cb * 64 + half * 32;
#pragma unroll 8
        for (int j = 0; j < 32; j++) {
            int col = colBaseT + j;
            if (col < Vc) {
                float v = stg[myrow * 65 + half * 32 + j] + s_bias[half * 32 + j];
                if (v > runMax) {
                    runSum = runSum * expf(runMax - v) + 1.f;
                    runMax = v; runIdx = col;
                } else {
                    runSum += expf(v - runMax);
                }
                if (col == tgt) sel = v;
            }
        }
        __syncthreads();
    }

    float oMax = __shfl_xor_sync(0xffffffffu, runMax, 1);
    float oSum = __shfl_xor_sync(0xffffffffu, runSum, 1);
    float oSel = __shfl_xor_sync(0xffffffffu, sel, 1);
    int   oIdx = __shfl_xor_sync(0xffffffffu, runIdx, 1);
    float M = fmaxf(runMax, oMax);
    float S = runSum * expf(runMax - M) + oSum * expf(oMax - M);
    int I = (oMax > runMax || (oMax == runMax && oIdx < runIdx)) ? oIdx : runIdx;
    float SEL = sel + oSel;

    float* lred = (float*)(smc + QH_RED);
    float* cred = lred + 128;
    if (half == 0) {
        lred[myrow] = (M + logf(S)) - SEL;
        cred[myrow] = (I == tgt) ? 1.f : 0.f;
    }
    __syncthreads();
    for (int o = 64; o; o >>= 1) {
        if (tid < o) { lred[tid] += lred[tid + o]; cred[tid] += cred[tid + o]; }
        __syncthreads();
    }
    if (tid == 0) {
        g_qpart_loss[blockIdx.x] = lred[0];
        g_qpart_corr[blockIdx.x] = cred[0];
    }
}

// ------------- p-head ------------------------------------------------------
__global__ void k_p(const float* __restrict__ usw, const float* __restrict__ usb)
{
    int warp = threadIdx.x >> 5, lane = threadIdx.x & 31;
    int row = blockIdx.x * 8 + warp;
    int s = row >> 11, b = row & (Bc - 1);

    int xd, c1, c2;
    if (s == 0)       { xd = 0; c1 = -1; c2 = -1; }
    else if (s <= Tc) { xd = s; c1 = s - 1; c2 = -1; }
    else { int j = s - (Tc + 1); xd = Tc - 1 - j; c1 = (j <= Tc - 2) ? (Tc - 2 - j) : -1; c2 = j; }

    const float* px = g_Px + ((size_t)xd * Bc + b) * Hc;
    const float* tp = g_Tp + (size_t)b * Hc;
    const float* f1 = (c1 >= 0) ? (g_Pmf + ((size_t)c1 * Bc + b) * Hc) : (const float*)0;
    const float* f2 = (c2 >= 0) ? (g_Pmr + ((size_t)c2 * Bc + b) * Hc) : (const float*)0;

    float acc = 0.f;
#pragma unroll
    for (int i = 0; i < 2; i++) {
        int n = (lane + 32 * i) * 4;
        float4 v = *(const float4*)(px + n);
        float4 t4 = *(const float4*)(tp + n);
        v.x += t4.x; v.y += t4.y; v.z += t4.z; v.w += t4.w;
        if (f1) { float4 a4 = *(const float4*)(f1 + n); v.x+=a4.x; v.y+=a4.y; v.z+=a4.z; v.w+=a4.w; }
        if (f2) { float4 a4 = *(const float4*)(f2 + n); v.x+=a4.x; v.y+=a4.y; v.z+=a4.z; v.w+=a4.w; }
        v.x = fmaxf(v.x,0.f); v.y = fmaxf(v.y,0.f); v.z = fmaxf(v.z,0.f); v.w = fmaxf(v.w,0.f);
        float4 u = *(const float4*)(usw + n);
        acc += v.x*u.x + v.y*u.y + v.z*u.z + v.w*u.w;
    }
#pragma unroll
    for (int o = 16; o; o >>= 1) acc += __shfl_xor_sync(0xffffffffu, acc, o);

    __shared__ float sl[8], sc[8];
    if (lane == 0) {
        float p = acc + usb[0];
        int tchk = (s < Tc) ? 1 : 0;
        float loss = fmaxf(p, 0.f) - (tchk ? p : 0.f) + log1pf(expf(-fabsf(p)));
        float corr = (((p > 0.f) ? 1 : 0) == tchk) ? 1.f : 0.f;
        sl[warp] = loss; sc[warp] = corr;
    }
    __syncthreads();
    if (threadIdx.x == 0) {
        float a = 0.f, c = 0.f;
        for (int w = 0; w < 8; w++) { a += sl[w]; c += sc[w]; }
        g_ppart_loss[blockIdx.x] = a;
        g_ppart_corr[blockIdx.x] = c;
    }
}

__global__ void k_finalize(float* __restrict__ out)
{
    __shared__ float sq[256], sqc[256], sp[256], spc[256];
    int t = threadIdx.x;
    float a = 0.f, b = 0.f, c = 0.f, d = 0.f;
    for (int i = t; i < QP; i += 256) { a += g_qpart_loss[i]; b += g_qpart_corr[i]; }
    for (int i = t; i < PBLOCKS; i += 256) { c += g_ppart_loss[i]; d += g_ppart_corr[i]; }
    sq[t] = a; sqc[t] = b; sp[t] = c; spc[t] = d;
    __syncthreads();
    for (int o = 128; o; o >>= 1) {
        if (t < o) { sq[t]+=sq[t+o]; sqc[t]+=sqc[t+o]; sp[t]+=sp[t+o]; spc[t]+=spc[t+o]; }
        __syncthreads();
    }
    if (t == 0) {
        out[0] = sq[0]  / (float)Bc;
        out[1] = sp[0]  / (float)Bc;
        out[2] = sqc[0] / (float)DB;
        out[3] = spc[0] / (float)SB;
    }
}

// ---------------------------------------------------------------------------
extern "C" void kernel_launch(void* const* d_in, const int* in_sizes, int n_in,
                              void* d_out, int out_size)
{
    const int*   wid      = (const int*)  d_in[0];
    const float* tree_vec = (const float*)d_in[1];
    const float* emb      = (const float*)d_in[2];
    const float* Wz       = (const float*)d_in[3];
    const float* bz       = (const float*)d_in[4];
    const float* Wr       = (const float*)d_in[5];
    const float* Ur       = (const float*)d_in[6];
    const float* br       = (const float*)d_in[7];
    const float* Wh       = (const float*)d_in[8];
    const float* bh       = (const float*)d_in[9];
    const float* W_w      = (const float*)d_in[10];
    const float* W_b      = (const float*)d_in[11];
    const float* U_w      = (const float*)d_in[12];
    const float* U_b      = (const float*)d_in[13];
    const float* Wo_w     = (const float*)d_in[14];
    const float* Wo_b     = (const float*)d_in[15];
    const float* Us_w     = (const float*)d_in[16];
    const float* Us_b     = (const float*)d_in[17];
    float* out = (float*)d_out;

    cudaFuncSetAttribute(k_tcg,   cudaFuncAttributeMaxDynamicSharedMemorySize, TCG_DSM);
    cudaFuncSetAttribute(k_scan,  cudaFuncAttributeMaxDynamicSharedMemorySize, SC_DSM);
    cudaFuncSetAttribute(k_qhead, cudaFuncAttributeMaxDynamicSharedMemorySize, QH_DSM);

    // side stream + events (kernel_launch runs only twice: correctness + capture)
    cudaStream_t s2;
    cudaStreamCreateWithFlags(&s2, cudaStreamNonBlocking);
    cudaEvent_t evSplit, evSide, evPostm, evP;
    cudaEventCreateWithFlags(&evSplit, cudaEventDisableTiming);
    cudaEventCreateWithFlags(&evSide,  cudaEventDisableTiming);
    cudaEventCreateWithFlags(&evPostm, cudaEventDisableTiming);
    cudaEventCreateWithFlags(&evP,     cudaEventDisableTiming);

    // stream 0: splits (needed by all GEMMs)
    k_split_w<<<WROWS, 256>>>(Wz, Wh, Wr, Ur, U_w, W_w, Wo_w);
    k_split_emb<<<Vc, 256>>>(emb);
    cudaEventRecord(evSplit, 0);

    // side stream: tree + Px (mode 3) — overlaps the scan's idle SMs
    cudaStreamWaitEvent(s2, evSplit, 0);
    k_tree<<<dim3(Bc, 2), 256, 0, s2>>>(tree_vec, W_w, W_b, U_w, U_b);
    k_tcg<<<dim3(DB/128, 4, 1), 256, TCG_DSM, s2>>>(3, wid, bz, bh, br);
    cudaEventRecord(evSide, s2);

    // stream 0: Az/Ah/Ar -> scan -> postm (Pq/Pmf/Pmr)
    k_tcg<<<dim3(DB/128, 4, 3), 256, TCG_DSM>>>(0, wid, bz, bh, br);
    k_scan<<<128, 512, SC_DSM>>>();
    k_tcg<<<dim3(TB/128, 4, 3), 256, TCG_DSM>>>(4, wid, bz, bh, br);
    cudaEventRecord(evPostm, 0);

    // side stream: k_p (needs Px+Tp from s2 order, Pmf/Pmr via evPostm)
    cudaStreamWaitEvent(s2, evPostm, 0);
    k_p<<<PBLOCKS, 256, 0, s2>>>(Us_w, Us_b);
    cudaEventRecord(evP, s2);

    // stream 0: qhead (needs Pq + Tq via evSide), then finalize after k_p
    cudaStreamWaitEvent(0, evSide, 0);
    k_qhead<<<DB/128, 256, QH_DSM>>>(wid, Wo_b);
    cudaStreamWaitEvent(0, evP, 0);
    k_finalize<<<1, 256>>>(out);
}

// round 17
// speedup vs baseline: 1.4227x; 1.0167x over previous
#include <cuda_runtime.h>
#include <cuda_bf16.h>
#include <math.h>
#include <stdint.h>

#define Bc 2048
#define Dc 24
#define Hc 256
#define Lc 64
#define Vc 780
#define Tc 23
#define Sc 47
#define DB (Dc*Bc)
#define TB (Tc*Bc)
#define SB (Sc*Bc)
#define QP (DB/128)
#define PBLOCKS (SB/8)
#define WROWS 3200

// ---------------- fp32 scratch ---------------------------------------------
__device__ float g_Az[DB*Hc];
__device__ float g_Ah[DB*Hc];
__device__ float g_Ar[DB*Hc];
__device__ float g_Px[DB*Hc];
__device__ float g_Pq [TB*Hc];
__device__ float g_Pmf[TB*Hc];
__device__ float g_Pmr[TB*Hc];
__device__ float g_Tq[Bc*Hc];
__device__ float g_Tp[Bc*Hc];
__device__ float g_qpart_loss[QP];
__device__ float g_qpart_corr[QP];
__device__ float g_ppart_loss[PBLOCKS];
__device__ float g_ppart_corr[PBLOCKS];
// bf16 split planes
__device__ __nv_bfloat16 g_wH[(size_t)WROWS*Hc];
__device__ __nv_bfloat16 g_wL[(size_t)WROWS*Hc];
__device__ __nv_bfloat16 g_eH[(size_t)Vc*Hc];
__device__ __nv_bfloat16 g_eL[(size_t)Vc*Hc];
__device__ __nv_bfloat16 g_mH[(size_t)2*TB*Hc];   // [dir][t*Bc+b][Hc]
__device__ __nv_bfloat16 g_mL[(size_t)2*TB*Hc];

__device__ __forceinline__ float sigf(float x) { return 1.f / (1.f + expf(-x)); }

// =================== mma.sync core =========================================
__device__ __forceinline__ uint32_t s2u(const void* p) {
    uint32_t a;
    asm("{ .reg .u64 t; cvta.to.shared.u64 t, %1; cvt.u32.u64 %0, t; }" : "=r"(a) : "l"(p));
    return a;
}
__device__ __forceinline__ void ldsm4(uint32_t& r0, uint32_t& r1, uint32_t& r2, uint32_t& r3, uint32_t a) {
    asm volatile("ldmatrix.sync.aligned.m8n8.x4.shared.b16 {%0,%1,%2,%3}, [%4];"
        : "=r"(r0), "=r"(r1), "=r"(r2), "=r"(r3) : "r"(a));
}
__device__ __forceinline__ void mma16816(float* d,
    uint32_t a0, uint32_t a1, uint32_t a2, uint32_t a3, uint32_t b0, uint32_t b1) {
    asm volatile("mma.sync.aligned.m16n8k16.row.col.f32.bf16.bf16.f32 "
        "{%0,%1,%2,%3}, {%4,%5,%6,%7}, {%8,%9}, {%0,%1,%2,%3};"
        : "+f"(d[0]), "+f"(d[1]), "+f"(d[2]), "+f"(d[3])
        : "r"(a0), "r"(a1), "r"(a2), "r"(a3), "r"(b0), "r"(b1));
}
__device__ __forceinline__ void pass_mma(uint32_t aAddr, uint32_t bAddr, float acc[2][4][4]) {
    uint32_t b0, b1, b2, b3, b4, b5, b6, b7;
    ldsm4(b0, b1, b2, b3, bAddr);
    ldsm4(b4, b5, b6, b7, bAddr + 1280);
#pragma unroll
    for (int mf = 0; mf < 2; mf++) {
        uint32_t a0, a1, a2, a3;
        ldsm4(a0, a1, a2, a3, aAddr + mf * 1280);
        mma16816(acc[mf][0], a0, a1, a2, a3, b0, b1);
        mma16816(acc[mf][1], a0, a1, a2, a3, b2, b3);
        mma16816(acc[mf][2], a0, a1, a2, a3, b4, b5);
        mma16816(acc[mf][3], a0, a1, a2, a3, b6, b7);
    }
}
// load-hoisted fused 3-product pass (8 ldsm then 24 mma) — 1 CTA/SM kernels only
__device__ __forceinline__ void pass3(uint32_t ah, uint32_t al, uint32_t bh, uint32_t bl,
                                      float acc[2][4][4]) {
    uint32_t h0,h1,h2,h3,h4,h5,h6,h7, l0,l1,l2,l3,l4,l5,l6,l7;
    ldsm4(h0,h1,h2,h3, bh); ldsm4(h4,h5,h6,h7, bh + 1280);
    ldsm4(l0,l1,l2,l3, bl); ldsm4(l4,l5,l6,l7, bl + 1280);
#pragma unroll
    for (int mf = 0; mf < 2; mf++) {
        uint32_t a0,a1,a2,a3, c0,c1,c2,c3;
        ldsm4(a0,a1,a2,a3, ah + mf * 1280);
        ldsm4(c0,c1,c2,c3, al + mf * 1280);
        mma16816(acc[mf][0], a0,a1,a2,a3, h0,h1);
        mma16816(acc[mf][1], a0,a1,a2,a3, h2,h3);
        mma16816(acc[mf][2], a0,a1,a2,a3, h4,h5);
        mma16816(acc[mf][3], a0,a1,a2,a3, h6,h7);
        mma16816(acc[mf][0], a0,a1,a2,a3, l0,l1);
        mma16816(acc[mf][1], a0,a1,a2,a3, l2,l3);
        mma16816(acc[mf][2], a0,a1,a2,a3, l4,l5);
        mma16816(acc[mf][3], a0,a1,a2,a3, l6,l7);
        mma16816(acc[mf][0], c0,c1,c2,c3, h0,h1);
        mma16816(acc[mf][1], c0,c1,c2,c3, h2,h3);
        mma16816(acc[mf][2], c0,c1,c2,c3, h4,h5);
        mma16816(acc[mf][3], c0,c1,c2,c3, h6,h7);
    }
}
// 16-col-strip fused 3-product pass for the 512-thread scan (6 ldsm, 12 mma)
__device__ __forceinline__ void pass3_16(uint32_t ah, uint32_t al, uint32_t bh, uint32_t bl,
                                         float acc[2][2][4]) {
    uint32_t h0,h1,h2,h3, l0,l1,l2,l3;
    ldsm4(h0,h1,h2,h3, bh);
    ldsm4(l0,l1,l2,l3, bl);
#pragma unroll
    for (int mf = 0; mf < 2; mf++) {
        uint32_t a0,a1,a2,a3, c0,c1,c2,c3;
        ldsm4(a0,a1,a2,a3, ah + mf * 1280);
        ldsm4(c0,c1,c2,c3, al + mf * 1280);
        mma16816(acc[mf][0], a0,a1,a2,a3, h0,h1);
        mma16816(acc[mf][1], a0,a1,a2,a3, h2,h3);
        mma16816(acc[mf][0], a0,a1,a2,a3, l0,l1);
        mma16816(acc[mf][1], a0,a1,a2,a3, l2,l3);
        mma16816(acc[mf][0], c0,c1,c2,c3, h0,h1);
        mma16816(acc[mf][1], c0,c1,c2,c3, h2,h3);
    }
}
__device__ __forceinline__ uint32_t aLaneOff(int lane, int wm) {
    return (uint32_t)((lane & 15) * 80 + (lane >> 4) * 16 + wm * 2560);
}
__device__ __forceinline__ uint32_t bLaneOff(int lane, int wn) {
    return (uint32_t)((((lane & 7) + ((lane >> 4) & 1) * 8)) * 80 + ((lane >> 3) & 1) * 16 + wn * 2560);
}
__device__ __forceinline__ uint32_t packbf2(float a, float b) {
    __nv_bfloat162 v = __floats2bfloat162_rn(a, b);
    return *(uint32_t*)&v;
}
__device__ __forceinline__ float2 unpack2(uint32_t h, uint32_t l) {
    __nv_bfloat162 H = *(__nv_bfloat162*)&h, L = *(__nv_bfloat162*)&l;
    return make_float2(__bfloat162float(H.x) + __bfloat162float(L.x),
                       __bfloat162float(H.y) + __bfloat162float(L.y));
}
// ---- cp.async helpers ----
__device__ __forceinline__ void cpa16(uint32_t dst, const void* src) {
    asm volatile("cp.async.cg.shared.global [%0], [%1], 16;" :: "r"(dst), "l"(src));
}
#define CPC()  asm volatile("cp.async.commit_group;" ::: "memory")
#define CPW(n) asm volatile("cp.async.wait_group %0;" :: "n"(n) : "memory")

// ------------- split/convert kernels ---------------------------------------
__global__ void k_split_w(const float* __restrict__ Wz, const float* __restrict__ Wh,
                          const float* __restrict__ Wr, const float* __restrict__ Ur,
                          const float* __restrict__ U_w, const float* __restrict__ W_w,
                          const float* __restrict__ Wo_w)
{
    int r = blockIdx.x, c = threadIdx.x;
    float v;
    if      (r < 256)  v = Wz[r * 512 + c];
    else if (r < 512)  v = Wh[(r - 256) * 512 + c];
    else if (r < 768)  v = Wr[(r - 512) * 256 + c];
    else if (r < 1024) v = U_w[(r - 768) * 576 + c];
    else if (r < 1280) v = W_w[(r - 1024) * 320 + c];
    else if (r < 1536) v = U_w[(r - 1280) * 576 + 256 + c];
    else if (r < 2432) { int w = r - 1536; v = (w < Vc) ? Wo_w[(size_t)w * 256 + c] : 0.f; }
    else if (r < 2688) v = Wz[(r - 2432) * 512 + 256 + c];
    else if (r < 2944) v = Wh[(r - 2688) * 512 + 256 + c];
    else               v = Ur[(r - 2944) * 256 + c];
    __nv_bfloat16 h = __float2bfloat16(v);
    g_wH[(size_t)r * 256 + c] = h;
    g_wL[(size_t)r * 256 + c] = __float2bfloat16(v - __bfloat162float(h));
}

__global__ void k_split_emb(const float* __restrict__ emb)
{
    int r = blockIdx.x, c = threadIdx.x;
    float v = emb[(size_t)r * 256 + c];
    __nv_bfloat16 h = __float2bfloat16(v);
    g_eH[(size_t)r * 256 + c] = h;
    g_eL[(size_t)r * 256 + c] = __float2bfloat16(v - __bfloat162float(h));
}

// ------------- generic big GEMM (HMMA, CTA 128x64, double-buffered) --------
#define TCG_BUF 30720
#define TCG_DSM 61440
__global__ void __launch_bounds__(256, 3) k_tcg(int modeBase, const int* __restrict__ wid,
                      const float* __restrict__ bz, const float* __restrict__ bh,
                      const float* __restrict__ br)
{
    extern __shared__ char smc[];
    uint32_t smb = s2u(smc);
    int tid = threadIdx.x, lane = tid & 31, warp = tid >> 5;
    int wm = warp >> 1, wn = warp & 1;
    int mode = modeBase + blockIdx.z;
    int rowBase = blockIdx.x * 128, colBase = blockIdx.y * 64;

    int wbase; float* outp; const float* bias;
    switch (mode) {
        case 0: wbase = 0;    outp = g_Az;  bias = bz; break;
        case 1: wbase = 256;  outp = g_Ah;  bias = bh; break;
        case 2: wbase = 512;  outp = g_Ar;  bias = br; break;
        case 3: wbase = 768;  outp = g_Px;  bias = 0;  break;
        case 4: wbase = 1024; outp = g_Pq;  bias = 0;  break;
        case 5: wbase = 1280; outp = g_Pmf; bias = 0;  break;
        default: wbase = 1280; outp = g_Pmr; bias = 0; break;
    }

    const uint4 *aHp[2], *aLp[2];
    uint32_t aStore[2];
#pragma unroll
    for (int j = 0; j < 2; j++) {
        int idx = tid + j * 256;
        int row = idx >> 2, q = idx & 3;
        aStore[j] = (uint32_t)(row * 80 + q * 16);
        int rA = rowBase + row;
        if (mode < 4) {
            int d = rA >> 11, b = rA & 2047;
            int sr = wid[b * Dc + d];
            aHp[j] = (const uint4*)(g_eH + (size_t)sr * 256 + q * 8);
            aLp[j] = (const uint4*)(g_eL + (size_t)sr * 256 + q * 8);
        } else {
            size_t rs = (size_t)((mode == 6) ? TB : 0) + rA;
            aHp[j] = (const uint4*)(g_mH + rs * 256 + q * 8);
            aLp[j] = (const uint4*)(g_mL + rs * 256 + q * 8);
        }
    }
    int bRow = tid >> 2, bQ = tid & 3;
    uint32_t bStore = (uint32_t)(bRow * 80 + bQ * 16);
    const uint4* bHp = (const uint4*)(g_wH + (size_t)(wbase + colBase + bRow) * 256 + bQ * 8);
    const uint4* bLp = (const uint4*)(g_wL + (size_t)(wbase + colBase + bRow) * 256 + bQ * 8);

    uint32_t aOff = aLaneOff(lane, wm), bOff = bLaneOff(lane, wn);
    float acc[2][4][4] = {};

    auto stage = [&](int kc) {
        uint32_t bo = smb + (uint32_t)((kc & 1) * TCG_BUF);
#pragma unroll
        for (int j = 0; j < 2; j++) {
            cpa16(bo + aStore[j],         aHp[j] + kc * 4);
            cpa16(bo + 10240 + aStore[j], aLp[j] + kc * 4);
        }
        cpa16(bo + 20480 + bStore, bHp + kc * 4);
        cpa16(bo + 25600 + bStore, bLp + kc * 4);
        CPC();
    };

    stage(0);
    for (int kc = 0; kc < 8; kc++) {
        if (kc < 7) { stage(kc + 1); CPW(1); }
        else        { CPW(0); }
        __syncthreads();
        uint32_t bo = smb + (uint32_t)((kc & 1) * TCG_BUF);
#pragma unroll
        for (int kk = 0; kk < 2; kk++) {
            uint32_t kb = kk * 32;
            pass_mma(bo + aOff + kb,         bo + 20480 + bOff + kb, acc);
            pass_mma(bo + aOff + kb,         bo + 25600 + bOff + kb, acc);
            pass_mma(bo + 10240 + aOff + kb, bo + 20480 + bOff + kb, acc);
        }
        __syncthreads();
    }

    float* stg = (float*)smc + warp * (32 * 33);
#pragma unroll
    for (int mf = 0; mf < 2; mf++)
#pragma unroll
        for (int nf = 0; nf < 4; nf++) {
            int r = mf * 16 + (lane >> 2);
            int c = nf * 8 + ((lane & 3) << 1);
            stg[r * 33 + c]           = acc[mf][nf][0];
            stg[r * 33 + c + 1]       = acc[mf][nf][1];
            stg[(r + 8) * 33 + c]     = acc[mf][nf][2];
            stg[(r + 8) * 33 + c + 1] = acc[mf][nf][3];
        }
    __syncwarp();
    int colg = colBase + wn * 32 + lane;
    float bval = bias ? bias[colg] : 0.f;
#pragma unroll 8
    for (int r = 0; r < 32; r++) {
        int rowg = rowBase + wm * 32 + r;
        outp[(size_t)rowg * 256 + colg] = stg[r * 33 + lane] + bval;
    }
}

// ------------- tree_vec small GEMMs ----------------------------------------
__global__ void k_tree(const float* __restrict__ tv,
                       const float* __restrict__ W_w, const float* __restrict__ W_b,
                       const float* __restrict__ U_w, const float* __restrict__ U_b)
{
    int b = blockIdx.x, z = blockIdx.y, n = threadIdx.x;
    __shared__ float s_tv[Lc];
    if (n < Lc) s_tv[n] = tv[(size_t)b * Lc + n];
    __syncthreads();
    const float* W; int ld, koff; const float* bias; float* out;
    if (z == 0) { W = W_w; ld = Hc + Lc;   koff = Hc;   bias = W_b; out = g_Tq; }
    else        { W = U_w; ld = 2*Hc + Lc; koff = 2*Hc; bias = U_b; out = g_Tp; }
    const float* wr = W + (size_t)n * ld + koff;
    float s = bias[n];
#pragma unroll
    for (int k = 0; k < Lc; k += 4) {
        float4 w4 = *(const float4*)(wr + k);
        s += s_tv[k]*w4.x + s_tv[k+1]*w4.y + s_tv[k+2]*w4.z + s_tv[k+3]*w4.w;
    }
    out[(size_t)b * Hc + n] = s;
}

// ------------- fused row-local scan (R11-proven: 512 threads) --------------
#define SC_MRES  0          /* 40960 */
#define SC_RMRES 40960      /* 40960 */
#define SC_BBUF  81920      /* 2 x 40960: per buf [H 20480 | L 20480] */
#define SC_AZ    163840     /* 32768 fp32 32x256 */
#define SC_AH    196608     /* 32768 */
#define SC_DSM   229376
__global__ void __launch_bounds__(512, 1) k_scan()
{
    extern __shared__ char smc[];
    uint32_t smb = s2u(smc);
    int tid = threadIdx.x, lane = tid & 31, warp = tid >> 5;  // warp 0..15
    int wn = warp;
    int dir = blockIdx.x >> 6;
    int rb = (blockIdx.x & 63) * 32;

    uint32_t aOff = aLaneOff(lane, 0);
    uint32_t bOff = (uint32_t)((((lane & 7) + ((lane >> 4) & 1) * 8)) * 80
                  + ((lane >> 3) & 1) * 16 + wn * 1280);

    for (int t = 0; t < Tc; t++) {
        int srcd = dir ? (Tc - t) : t;
        float accz[2][2][4] = {}, acch[2][2][4] = {};

        if (t > 0) {
            auto stage1 = [&](int kc) {
                uint32_t bo = smb + SC_BBUF + (uint32_t)((kc & 1) * 40960);
#pragma unroll
                for (int i = 0; i < 4; i++) {
                    int u = tid + i * 512;
                    int pl = u >= 1024;
                    int uu = u - pl * 1024;
                    int col = uu >> 2, q = uu & 3;
                    const __nv_bfloat16* src = (pl ? g_wL : g_wH) + (size_t)(2432 + col) * 256 + kc * 32 + q * 8;
                    cpa16(bo + pl * 20480 + col * 80 + q * 16, src);
                }
                CPC();
            };
            stage1(0);
            for (int kc = 0; kc < 8; kc++) {
                if (kc < 7) { stage1(kc + 1); CPW(1); }
                else        { CPW(0); }
                __syncthreads();
                uint32_t bo = smb + SC_BBUF + (uint32_t)((kc & 1) * 40960);
                uint32_t aH = smb + SC_MRES + kc * 5120 + aOff;
#pragma unroll
                for (int kk = 0; kk < 2; kk++) {
                    uint32_t kb = kk * 32;
                    pass3_16(aH + kb, aH + 2560 + kb,
                             bo + bOff + kb, bo + 20480 + bOff + kb, accz);
                }
                __syncthreads();
            }
            auto stage2 = [&](int kc) {
                uint32_t bo = smb + SC_BBUF + (uint32_t)((kc & 1) * 40960);
#pragma unroll
                for (int i = 0; i < 4; i++) {
                    int u = tid + i * 512;
                    int pl = u >= 1024;
                    int uu = u - pl * 1024;
                    int col = uu >> 2, q = uu & 3;
                    const __nv_bfloat16* src = (pl ? g_wL : g_wH) + (size_t)(2688 + col) * 256 + kc * 32 + q * 8;
                    cpa16(bo + pl * 20480 + col * 80 + q * 16, src);
                }
                {
                    int arr = tid >> 8;
                    int g = kc * 256 + (tid & 255);
                    int row = g >> 6, c16 = g & 63;
                    const float* src = (arr ? g_Ah : g_Az) + ((size_t)srcd * Bc + rb + row) * 256 + c16 * 4;
                    cpa16(smb + (arr ? SC_AH : SC_AZ) + row * 1024 + c16 * 16, src);
                }
                CPC();
            };
            stage2(0);
            for (int kc = 0; kc < 8; kc++) {
                if (kc < 7) { stage2(kc + 1); CPW(1); }
                else        { CPW(0); }
                __syncthreads();
                uint32_t bo = smb + SC_BBUF + (uint32_t)((kc & 1) * 40960);
                uint32_t aH = smb + SC_RMRES + kc * 5120 + aOff;
#pragma unroll
                for (int kk = 0; kk < 2; kk++) {
                    uint32_t kb = kk * 32;
                    pass3_16(aH + kb, aH + 2560 + kb,
                             bo + bOff + kb, bo + 20480 + bOff + kb, acch);
                }
                __syncthreads();
            }
        } else {
#pragma unroll
            for (int i = 0; i < 8; i++) {
                int g = tid + i * 512;
                int arr = g >> 11;
                int gg = g & 2047;
                int row = gg >> 6, c16 = gg & 63;
                const float* src = (arr ? g_Ah : g_Az) + ((size_t)srcd * Bc + rb + row) * 256 + c16 * 4;
                cpa16(smb + (arr ? SC_AH : SC_AZ) + row * 1024 + c16 * 16, src);
            }
            CPC(); CPW(0);
            __syncthreads();
        }

        size_t gRowBase = (size_t)dir * TB + (size_t)t * Bc + rb;
#pragma unroll
        for (int mf = 0; mf < 2; mf++)
#pragma unroll
            for (int nf = 0; nf < 2; nf++) {
#pragma unroll
                for (int h = 0; h < 2; h++) {
                    int row = mf * 16 + (lane >> 2) + h * 8;
                    int col = wn * 16 + nf * 8 + ((lane & 3) << 1);
                    float2 az = *(const float2*)(smc + SC_AZ + row * 1024 + col * 4);
                    float2 ah = *(const float2*)(smc + SC_AH + row * 1024 + col * 4);
                    int chunk = col >> 5, k = col & 31, q = k >> 3, byo = (k & 7) * 2;
                    uint32_t mo = SC_MRES + chunk * 5120 + row * 80 + q * 16 + byo;
                    float2 mp = make_float2(0.f, 0.f);
                    if (t > 0)
                        mp = unpack2(*(uint32_t*)(smc + mo), *(uint32_t*)(smc + mo + 2560));
                    float z0 = sigf(accz[mf][nf][h*2+0] + az.x);
                    float z1 = sigf(accz[mf][nf][h*2+1] + az.y);
                    float q0 = tanhf(acch[mf][nf][h*2+0] + ah.x);
                    float q1 = tanhf(acch[mf][nf][h*2+1] + ah.y);
                    float m0 = (1.f - z0) * mp.x + z0 * q0;
                    float m1 = (1.f - z1) * mp.y + z1 * q1;
                    __nv_bfloat16 h0 = __float2bfloat16(m0), h1 = __float2bfloat16(m1);
                    uint32_t hv = packbf2(__bfloat162float(h0), __bfloat162float(h1));
                    uint32_t lv = packbf2(m0 - __bfloat162float(h0), m1 - __bfloat162float(h1));
                    *(uint32_t*)(smc + mo) = hv;
                    *(uint32_t*)(smc + mo + 2560) = lv;
                    size_t po = (gRowBase + row) * 256 + col;
                    *(uint32_t*)(g_mH + po) = hv;
                    *(uint32_t*)(g_mL + po) = lv;
                }
            }
        __syncthreads();

        if (t == Tc - 1) break;

        {
            int dstd = dir ? (Tc - 1 - t) : (t + 1);
            float acc[2][2][4] = {};
            auto stage3 = [&](int kc) {
                uint32_t bo = smb + SC_BBUF + (uint32_t)((kc & 1) * 40960);
#pragma unroll
                for (int i = 0; i < 4; i++) {
                    int u = tid + i * 512;
                    int pl = u >= 1024;
                    int uu = u - pl * 1024;
                    int col = uu >> 2, q = uu & 3;
                    const __nv_bfloat16* src = (pl ? g_wL : g_wH) + (size_t)(2944 + col) * 256 + kc * 32 + q * 8;
                    cpa16(bo + pl * 20480 + col * 80 + q * 16, src);
                }
                if (tid < 256) {
                    int g = kc * 256 + tid;
                    int row = g >> 6, c16 = g & 63;
                    const float* src = g_Ar + ((size_t)dstd * Bc + rb + row) * 256 + c16 * 4;
                    cpa16(smb + SC_AZ + row * 1024 + c16 * 16, src);
                }
                CPC();
            };
            stage3(0);
            for (int kc = 0; kc < 8; kc++) {
                if (kc < 7) { stage3(kc + 1); CPW(1); }
                else        { CPW(0); }
                __syncthreads();
                uint32_t bo = smb + SC_BBUF + (uint32_t)((kc & 1) * 40960);
                uint32_t aH = smb + SC_MRES + kc * 5120 + aOff;
#pragma unroll
                for (int kk = 0; kk < 2; kk++) {
                    uint32_t kb = kk * 32;
                    pass3_16(aH + kb, aH + 2560 + kb,
                             bo + bOff + kb, bo + 20480 + bOff + kb, acc);
                }
                __syncthreads();
            }
#pragma unroll
            for (int mf = 0; mf < 2; mf++)
#pragma unroll
                for (int nf = 0; nf < 2; nf++) {
#pragma unroll
                    for (int h = 0; h < 2; h++) {
                        int row = mf * 16 + (lane >> 2) + h * 8;
                        int col = wn * 16 + nf * 8 + ((lane & 3) << 1);
                        float2 ar = *(const float2*)(smc + SC_AZ + row * 1024 + col * 4);
                        int chunk = col >> 5, k = col & 31, q = k >> 3, byo = (k & 7) * 2;
                        uint32_t mo = SC_MRES + chunk * 5120 + row * 80 + q * 16 + byo;
                        float2 mc = unpack2(*(uint32_t*)(smc + mo), *(uint32_t*)(smc + mo + 2560));
                        float r0 = sigf(acc[mf][nf][h*2+0] + ar.x);
                        float r1 = sigf(acc[mf][nf][h*2+1] + ar.y);
                        float rm0 = r0 * mc.x, rm1 = r1 * mc.y;
                        __nv_bfloat16 h0 = __float2bfloat16(rm0), h1 = __float2bfloat16(rm1);
                        uint32_t ro = SC_RMRES + chunk * 5120 + row * 80 + q * 16 + byo;
                        *(uint32_t*)(smc + ro) = packbf2(__bfloat162float(h0), __bfloat162float(h1));
                        *(uint32_t*)(smc + ro + 2560) = packbf2(rm0 - __bfloat162float(h0), rm1 - __bfloat162float(h1));
                    }
                }
            __syncthreads();
        }
    }
}

// ------------- fused q-head ------------------------------------------------
#define QH_B0   163840
#define QH_STG  184320
#define QH_BIAS 217600
#define QH_RED  217856
#define QH_DSM  218880
__global__ void k_qhead(const int* __restrict__ wid, const float* __restrict__ Wob)
{
    extern __shared__ char smc[];
    uint32_t smb = s2u(smc);
    int tid = threadIdx.x, lane = tid & 31, warp = tid >> 5;
    int wm = warp >> 1, wn = warp & 1;
    int rowBase = blockIdx.x * 128;

    for (int it = 0; it < 16; it++) {
        int idx = tid + it * 256;
        int row = idx >> 5, rem = idx & 31, kc = rem >> 2, q = rem & 3;
        int rA = rowBase + row, d = rA >> 11, b = rA & 2047;
        int k0 = kc * 32 + q * 8;
        const float4* tq = (const float4*)(g_Tq + (size_t)b * 256 + k0);
        float4 v0 = tq[0], v1 = tq[1];
        if (d) {
            const float4* pq = (const float4*)(g_Pq + ((size_t)(d - 1) * Bc + b) * 256 + k0);
            float4 p0 = pq[0], p1 = pq[1];
            v0.x += p0.x; v0.y += p0.y; v0.z += p0.z; v0.w += p0.w;
            v1.x += p1.x; v1.y += p1.y; v1.z += p1.z; v1.w += p1.w;
        }
        float vv[8] = { fmaxf(v0.x,0.f), fmaxf(v0.y,0.f), fmaxf(v0.z,0.f), fmaxf(v0.w,0.f),
                        fmaxf(v1.x,0.f), fmaxf(v1.y,0.f), fmaxf(v1.z,0.f), fmaxf(v1.w,0.f) };
        union { uint4 u; __nv_bfloat16 b8[8]; } Hx, Lx;
#pragma unroll
        for (int e = 0; e < 8; e++) {
            Hx.b8[e] = __float2bfloat16(vv[e]);
            Lx.b8[e] = __float2bfloat16(vv[e] - __bfloat162float(Hx.b8[e]));
        }
        uint32_t off = (uint32_t)(kc * 10240 + row * 80 + q * 16);
        *(uint4*)(smc + off) = Hx.u;
        *(uint4*)(smc + 81920 + off) = Lx.u;
    }
    __syncthreads();

    int myrow = tid >> 1, half = tid & 1;
    int rA0 = rowBase + myrow;
    int tgt = wid[(rA0 & 2047) * Dc + (rA0 >> 11)];
    float runMax = -3.4e38f, runSum = 0.f, sel = 0.f;
    int runIdx = Vc;

    uint32_t aOff = aLaneOff(lane, wm), bOff = bLaneOff(lane, wn);
    int bRow = tid >> 2, bQ = tid & 3;
    uint32_t bStore = (uint32_t)(bRow * 80 + bQ * 16);
    float* stg = (float*)(smc + QH_STG);
    float* s_bias = (float*)(smc + QH_BIAS);

    for (int cb = 0; cb < 13; cb++) {
        if (tid < 64) {
            int colg = cb * 64 + tid;
            s_bias[tid] = (colg < Vc) ? Wob[colg] : 0.f;
        }
        float acc[2][4][4] = {};
        const uint4* bh = (const uint4*)(g_wH + (size_t)(1536 + cb * 64 + bRow) * 256 + bQ * 8);
        const uint4* bl = (const uint4*)(g_wL + (size_t)(1536 + cb * 64 + bRow) * 256 + bQ * 8);
        auto stageB = [&](int kc) {
            uint32_t bo = smb + QH_B0 + (uint32_t)((kc & 1) * 10240);
            cpa16(bo + bStore, bh + kc * 4);
            cpa16(bo + 5120 + bStore, bl + kc * 4);
            CPC();
        };
        stageB(0);
        for (int kc = 0; kc < 8; kc++) {
            if (kc < 7) { stageB(kc + 1); CPW(1); }
            else        { CPW(0); }
            __syncthreads();
            uint32_t bo = smb + QH_B0 + (uint32_t)((kc & 1) * 10240);
#pragma unroll
            for (int kk = 0; kk < 2; kk++) {
                uint32_t kb = kk * 32;
                pass3(smb + kc * 10240 + aOff + kb,
                      smb + 81920 + kc * 10240 + aOff + kb,
                      bo + bOff + kb,
                      bo + 5120 + bOff + kb, acc);
            }
            __syncthreads();
        }
#pragma unroll
        for (int mf = 0; mf < 2; mf++)
#pragma unroll
            for (int nf = 0; nf < 4; nf++) {
                int r = wm * 32 + mf * 16 + (lane >> 2);
                int c = wn * 32 + nf * 8 + ((lane & 3) << 1);
                stg[r * 65 + c]           = acc[mf][nf][0];
                stg[r * 65 + c + 1]       = acc[mf][nf][1];
                stg[(r + 8) * 65 + c]     = acc[mf][nf][2];
                stg[(r + 8) * 65 + c + 1] = acc[mf][nf][3];
            }
        __syncthreads();
        int colBaseT = cb * 64 + half * 32;
#pragma unroll 8
        for (int j = 0; j < 32; j++) {
            int col = colBaseT + j;
            if (col < Vc) {
                float v = stg[myrow * 65 + half * 32 + j] + s_bias[half * 32 + j];
                if (v > runMax) {
                    runSum = runSum * expf(runMax - v) + 1.f;
                    runMax = v; runIdx = col;
                } else {
                    runSum += expf(v - runMax);
                }
                if (col == tgt) sel = v;
            }
        }
        __syncthreads();
    }

    float oMax = __shfl_xor_sync(0xffffffffu, runMax, 1);
    float oSum = __shfl_xor_sync(0xffffffffu, runSum, 1);
    float oSel = __shfl_xor_sync(0xffffffffu, sel, 1);
    int   oIdx = __shfl_xor_sync(0xffffffffu, runIdx, 1);
    float M = fmaxf(runMax, oMax);
    float S = runSum * expf(runMax - M) + oSum * expf(oMax - M);
    int I = (oMax > runMax || (oMax == runMax && oIdx < runIdx)) ? oIdx : runIdx;
    float SEL = sel + oSel;

    float* lred = (float*)(smc + QH_RED);
    float* cred = lred + 128;
    if (half == 0) {
        lred[myrow] = (M + logf(S)) - SEL;
        cred[myrow] = (I == tgt) ? 1.f : 0.f;
    }
    __syncthreads();
    for (int o = 64; o; o >>= 1) {
        if (tid < o) { lred[tid] += lred[tid + o]; cred[tid] += cred[tid + o]; }
        __syncthreads();
    }
    if (tid == 0) {
        g_qpart_loss[blockIdx.x] = lred[0];
        g_qpart_corr[blockIdx.x] = cred[0];
    }
}

// ------------- p-head ------------------------------------------------------
__global__ void k_p(const float* __restrict__ usw, const float* __restrict__ usb)
{
    int warp = threadIdx.x >> 5, lane = threadIdx.x & 31;
    int row = blockIdx.x * 8 + warp;
    int s = row >> 11, b = row & (Bc - 1);

    int xd, c1, c2;
    if (s == 0)       { xd = 0; c1 = -1; c2 = -1; }
    else if (s <= Tc) { xd = s; c1 = s - 1; c2 = -1; }
    else { int j = s - (Tc + 1); xd = Tc - 1 - j; c1 = (j <= Tc - 2) ? (Tc - 2 - j) : -1; c2 = j; }

    const float* px = g_Px + ((size_t)xd * Bc + b) * Hc;
    const float* tp = g_Tp + (size_t)b * Hc;
    const float* f1 = (c1 >= 0) ? (g_Pmf + ((size_t)c1 * Bc + b) * Hc) : (const float*)0;
    const float* f2 = (c2 >= 0) ? (g_Pmr + ((size_t)c2 * Bc + b) * Hc) : (const float*)0;

    float acc = 0.f;
#pragma unroll
    for (int i = 0; i < 2; i++) {
        int n = (lane + 32 * i) * 4;
        float4 v = *(const float4*)(px + n);
        float4 t4 = *(const float4*)(tp + n);
        v.x += t4.x; v.y += t4.y; v.z += t4.z; v.w += t4.w;
        if (f1) { float4 a4 = *(const float4*)(f1 + n); v.x+=a4.x; v.y+=a4.y; v.z+=a4.z; v.w+=a4.w; }
        if (f2) { float4 a4 = *(const float4*)(f2 + n); v.x+=a4.x; v.y+=a4.y; v.z+=a4.z; v.w+=a4.w; }
        v.x = fmaxf(v.x,0.f); v.y = fmaxf(v.y,0.f); v.z = fmaxf(v.z,0.f); v.w = fmaxf(v.w,0.f);
        float4 u = *(const float4*)(usw + n);
        acc += v.x*u.x + v.y*u.y + v.z*u.z + v.w*u.w;
    }
#pragma unroll
    for (int o = 16; o; o >>= 1) acc += __shfl_xor_sync(0xffffffffu, acc, o);

    __shared__ float sl[8], sc[8];
    if (lane == 0) {
        float p = acc + usb[0];
        int tchk = (s < Tc) ? 1 : 0;
        float loss = fmaxf(p, 0.f) - (tchk ? p : 0.f) + log1pf(expf(-fabsf(p)));
        float corr = (((p > 0.f) ? 1 : 0) == tchk) ? 1.f : 0.f;
        sl[warp] = loss; sc[warp] = corr;
    }
    __syncthreads();
    if (threadIdx.x == 0) {
        float a = 0.f, c = 0.f;
        for (int w = 0; w < 8; w++) { a += sl[w]; c += sc[w]; }
        g_ppart_loss[blockIdx.x] = a;
        g_ppart_corr[blockIdx.x] = c;
    }
}

__global__ void k_finalize(float* __restrict__ out)
{
    __shared__ float sq[256], sqc[256], sp[256], spc[256];
    int t = threadIdx.x;
    float a = 0.f, b = 0.f, c = 0.f, d = 0.f;
    for (int i = t; i < QP; i += 256) { a += g_qpart_loss[i]; b += g_qpart_corr[i]; }
    for (int i = t; i < PBLOCKS; i += 256) { c += g_ppart_loss[i]; d += g_ppart_corr[i]; }
    sq[t] = a; sqc[t] = b; sp[t] = c; spc[t] = d;
    __syncthreads();
    for (int o = 128; o; o >>= 1) {
        if (t < o) { sq[t]+=sq[t+o]; sqc[t]+=sqc[t+o]; sp[t]+=sp[t+o]; spc[t]+=spc[t+o]; }
        __syncthreads();
    }
    if (t == 0) {
        out[0] = sq[0]  / (float)Bc;
        out[1] = sp[0]  / (float)Bc;
        out[2] = sqc[0] / (float)DB;
        out[3] = spc[0] / (float)SB;
    }
}

// ---------------------------------------------------------------------------
extern "C" void kernel_launch(void* const* d_in, const int* in_sizes, int n_in,
                              void* d_out, int out_size)
{
    const int*   wid      = (const int*)  d_in[0];
    const float* tree_vec = (const float*)d_in[1];
    const float* emb      = (const float*)d_in[2];
    const float* Wz       = (const float*)d_in[3];
    const float* bz       = (const float*)d_in[4];
    const float* Wr       = (const float*)d_in[5];
    const float* Ur       = (const float*)d_in[6];
    const float* br       = (const float*)d_in[7];
    const float* Wh       = (const float*)d_in[8];
    const float* bh       = (const float*)d_in[9];
    const float* W_w      = (const float*)d_in[10];
    const float* W_b      = (const float*)d_in[11];
    const float* U_w      = (const float*)d_in[12];
    const float* U_b      = (const float*)d_in[13];
    const float* Wo_w     = (const float*)d_in[14];
    const float* Wo_b     = (const float*)d_in[15];
    const float* Us_w     = (const float*)d_in[16];
    const float* Us_b     = (const float*)d_in[17];
    float* out = (float*)d_out;

    cudaFuncSetAttribute(k_tcg,   cudaFuncAttributeMaxDynamicSharedMemorySize, TCG_DSM);
    cudaFuncSetAttribute(k_scan,  cudaFuncAttributeMaxDynamicSharedMemorySize, SC_DSM);
    cudaFuncSetAttribute(k_qhead, cudaFuncAttributeMaxDynamicSharedMemorySize, QH_DSM);

    cudaStream_t s2;
    cudaStreamCreateWithFlags(&s2, cudaStreamNonBlocking);
    cudaEvent_t evSplit, evSide, evScan, evP;
    cudaEventCreateWithFlags(&evSplit, cudaEventDisableTiming);
    cudaEventCreateWithFlags(&evSide,  cudaEventDisableTiming);
    cudaEventCreateWithFlags(&evScan,  cudaEventDisableTiming);
    cudaEventCreateWithFlags(&evP,     cudaEventDisableTiming);

    // stream 0: splits (needed by all GEMMs)
    k_split_w<<<WROWS, 256>>>(Wz, Wh, Wr, Ur, U_w, W_w, Wo_w);
    k_split_emb<<<Vc, 256>>>(emb);
    cudaEventRecord(evSplit, 0);

    // side stream: tree + Px (mode 3)
    cudaStreamWaitEvent(s2, evSplit, 0);
    k_tree<<<dim3(Bc, 2), 256, 0, s2>>>(tree_vec, W_w, W_b, U_w, U_b);
    k_tcg<<<dim3(DB/128, 4, 1), 256, TCG_DSM, s2>>>(3, wid, bz, bh, br);
    cudaEventRecord(evSide, s2);

    // stream 0: Az/Ah/Ar -> scan
    k_tcg<<<dim3(DB/128, 4, 3), 256, TCG_DSM>>>(0, wid, bz, bh, br);
    k_scan<<<128, 512, SC_DSM>>>();
    cudaEventRecord(evScan, 0);

    // stream 0: Pq (mode 4) -> qhead (needs Tq via evSide)
    k_tcg<<<dim3(TB/128, 4, 1), 256, TCG_DSM>>>(4, wid, bz, bh, br);
    cudaStreamWaitEvent(0, evSide, 0);
    k_qhead<<<DB/128, 256, QH_DSM>>>(wid, Wo_b);

    // side stream: Pmf/Pmr (modes 5-6) -> k_p (Px/Tp in s2 order)
    cudaStreamWaitEvent(s2, evScan, 0);
    k_tcg<<<dim3(TB/128, 4, 2), 256, TCG_DSM, s2>>>(5, wid, bz, bh, br);
    k_p<<<PBLOCKS, 256, 0, s2>>>(Us_w, Us_b);
    cudaEventRecord(evP, s2);

    // stream 0: finalize after both heads
    cudaStreamWaitEvent(0, evP, 0);
    k_finalize<<<1, 256>>>(out);
}